// round 12
// baseline (speedup 1.0000x reference)
#include <cuda_runtime.h>
#include <cuda_bf16.h>
#include <cstdint>

// ---------------------------------------------------------------------------
// LocalWindowTransformer on sm_103 (mma.sync tf32 path).
//   GEMM1: qkv = x @ Win^T + b_in   [16384 x 3072], K=1024
//   attn : per (window, head) online-softmax(qk^T/8)v  (fp32 FFMA2, LDS.128)
//   GEMM3: out = att @ Wout^T + b_out [16384 x 1024], K=1024
// tf32 single-product GEMM (mma.sync.m16n8k8, fp32 accum), inputs rna-rounded.
// R12: CTA 128x256, warp tile 64x64 (8 warps, 1 CTA/SM) -> LDS/MMA ratio 1.5x
//      down, tensor pipe becomes the sole binding resource.
// ---------------------------------------------------------------------------

#define M_TOK   16384
#define HDIM    1024
#define QKVDIM  3072
#define NHEAD   16
#define HD      64
#define WIN     128
#define NWIN    128

// ---- device scratch (no cudaMalloc allowed) --------------------------------
__device__ float g_qkv [(size_t)M_TOK * QKVDIM];    // 192 MiB
__device__ float g_xr  [(size_t)M_TOK * HDIM];      // 64 MiB (tf32-rounded x)
__device__ float g_wir [(size_t)QKVDIM * HDIM];     // 12 MiB
__device__ float g_wor [(size_t)HDIM * HDIM];       // 4 MiB
__device__ float g_att [(size_t)M_TOK * HDIM];      // 64 MiB (rounded attn out)

// ---- helpers ---------------------------------------------------------------
__device__ __forceinline__ uint32_t smem_u32(const void* p) {
    uint32_t a;
    asm("{ .reg .u64 t; cvta.to.shared.u64 t, %1; cvt.u32.u64 %0, t; }"
        : "=r"(a) : "l"(p));
    return a;
}
__device__ __forceinline__ void cp16(uint32_t dst, const void* src) {
    asm volatile("cp.async.cg.shared.global [%0], [%1], 16;"
                 :: "r"(dst), "l"(src));
}
__device__ __forceinline__ float rna_tf32(float v) {
    uint32_t r;
    asm("cvt.rna.tf32.f32 %0, %1;" : "=r"(r) : "f"(v));
    return __uint_as_float(r);
}

#define LDSM4(r, a) \
    asm volatile("ldmatrix.sync.aligned.m8n8.x4.shared.b16 {%0,%1,%2,%3}, [%4];" \
                 : "=r"((r)[0]), "=r"((r)[1]), "=r"((r)[2]), "=r"((r)[3]) \
                 : "r"(a))

#define MMAT(c, a, b0, b1) \
    asm volatile("mma.sync.aligned.m16n8k8.row.col.f32.tf32.tf32.f32 " \
                 "{%0,%1,%2,%3}, {%4,%5,%6,%7}, {%8,%9}, {%0,%1,%2,%3};" \
                 : "+f"((c)[0]), "+f"((c)[1]), "+f"((c)[2]), "+f"((c)[3]) \
                 : "r"((a)[0]), "r"((a)[1]), "r"((a)[2]), "r"((a)[3]), \
                   "r"(b0), "r"(b1))

// ---------------------------------------------------------------------------
// round fp32 -> tf32 (rna) elementwise. 1 thread = 4 values.
// ---------------------------------------------------------------------------
__global__ __launch_bounds__(256)
void round_tf32(const float4* __restrict__ src, float4* __restrict__ dst)
{
    int u = blockIdx.x * 256 + threadIdx.x;
    float4 v = src[u];
    v.x = rna_tf32(v.x); v.y = rna_tf32(v.y);
    v.z = rna_tf32(v.z); v.w = rna_tf32(v.w);
    dst[u] = v;
}

// ---------------------------------------------------------------------------
// tf32 NT GEMM: C[M,N] = A[M,1024] * B[N,1024]^T + bias
// BM=128, BN=256, BK=32 (fp32). 256 threads (8 warps 2x4), warp tile 64x64.
// smem: A 128x128B + B 256x128B per stage, XOR swizzle, 2-stage cp.async.
// 1 CTA/SM (high regs). ldmatrix.b16 view of fp32 -> tf32 fragments.
// ---------------------------------------------------------------------------
#define OFF_B  16384
#define STAGE  49152
#define KT     32               /* 1024 / 32 */
#define GEMM_SMEM (2 * STAGE)   /* 98304 B */

__global__ __launch_bounds__(256, 1)
void gemm_tf32(const float* __restrict__ A, const float* __restrict__ B,
               const float* __restrict__ bias, float* __restrict__ C, int N)
{
    extern __shared__ char smem_raw[];
    const uint32_t sb = smem_u32(smem_raw);

    const int tid  = threadIdx.x;
    const int lane = tid & 31;
    const int wid  = tid >> 5;
    const int wm   = wid & 1;           // 0..1  (64-row halves of 128)
    const int wn   = wid >> 1;          // 0..3  (64-col quarters of 256)
    const int bm   = blockIdx.x;
    const int bn   = blockIdx.y;

    // --- loaders ---
    // A: 128 rows x 8 units(16B): thread -> row=tid>>1, units (tid&1)*4..+3
    const int arow = tid >> 1;
    const int ahu  = (tid & 1) * 4;
    const int arm  = arow & 7;
    uint32_t dA[4];
#pragma unroll
    for (int i = 0; i < 4; ++i)
        dA[i] = arow * 128 + (((ahu + i) ^ arm) << 4);
    const float* pA = A + (size_t)(bm * 128 + arow) * 1024 + ahu * 4;

    // B: 256 rows x 8 units: thread -> row=tid, all 8 units
    const int brow = tid;
    const int brm  = brow & 7;
    uint32_t dB[8];
#pragma unroll
    for (int i = 0; i < 8; ++i)
        dB[i] = OFF_B + brow * 128 + ((i ^ brm) << 4);
    const float* pB = B + (size_t)(bn * 256 + brow) * 1024;

    auto issue = [&](uint32_t st, int ko) {
#pragma unroll
        for (int i = 0; i < 4; ++i)
            cp16(st + dA[i], pA + ko + i * 4);
#pragma unroll
        for (int i = 0; i < 8; ++i)
            cp16(st + dB[i], pB + ko + i * 4);
    };

    // --- ldmatrix row precompute ---
    int rowA[4], rmA[4];
#pragma unroll
    for (int mt = 0; mt < 4; ++mt) {
        rowA[mt] = wm * 64 + mt * 16 + ((lane >> 3) & 1) * 8 + (lane & 7);
        rmA[mt]  = rowA[mt] & 7;
    }
    const int uaA = lane >> 4;
    int rowB[4], rmB[4];
#pragma unroll
    for (int p = 0; p < 4; ++p) {
        rowB[p] = wn * 64 + p * 16 + (lane >> 4) * 8 + (lane & 7);
        rmB[p]  = rowB[p] & 7;
    }
    const int uaB = (lane >> 3) & 1;

    float acc[4][8][4];
#pragma unroll
    for (int i = 0; i < 4; ++i)
#pragma unroll
        for (int j = 0; j < 8; ++j)
#pragma unroll
            for (int k = 0; k < 4; ++k) acc[i][j][k] = 0.f;

    issue(sb, 0);
    asm volatile("cp.async.commit_group;" ::: "memory");

    for (int t = 0; t < KT; ++t) {
        if (t + 1 < KT) {
            issue(sb + ((t + 1) & 1) * STAGE, (t + 1) * 32);
            asm volatile("cp.async.commit_group;" ::: "memory");
            asm volatile("cp.async.wait_group 1;" ::: "memory");
        } else {
            asm volatile("cp.async.wait_group 0;" ::: "memory");
        }
        __syncthreads();                    // stage t visible

        const uint32_t st = sb + (t & 1) * STAGE;
#pragma unroll
        for (int ks = 0; ks < 4; ++ks) {
            uint32_t af[4][4], bf[4][4];
#pragma unroll
            for (int mt = 0; mt < 4; ++mt) {
                const uint32_t ad = st + rowA[mt] * 128 +
                                    (((ks * 2 + uaA) ^ rmA[mt]) << 4);
                LDSM4(af[mt], ad);
            }
#pragma unroll
            for (int p = 0; p < 4; ++p) {
                const uint32_t bd = st + OFF_B + rowB[p] * 128 +
                                    (((ks * 2 + uaB) ^ rmB[p]) << 4);
                LDSM4(bf[p], bd);
            }
#pragma unroll
            for (int mt = 0; mt < 4; ++mt) {
#pragma unroll
                for (int nt = 0; nt < 8; ++nt) {
                    const int p = nt >> 1, s = (nt & 1) * 2;
                    MMAT(acc[mt][nt], af[mt], bf[p][s], bf[p][s + 1]);
                }
            }
        }
        __syncthreads();                    // done reading stage t slot
    }

    // --- epilogue: register frags -> GMEM with bias ---
#pragma unroll
    for (int mt = 0; mt < 4; ++mt) {
#pragma unroll
        for (int nt = 0; nt < 8; ++nt) {
            const float* c = acc[mt][nt];
            const int row = bm * 128 + wm * 64 + mt * 16 + (lane >> 2);
            const int col = bn * 256 + wn * 64 + nt * 8 + (lane & 3) * 2;
            const float b0 = __ldg(bias + col);
            const float b1 = __ldg(bias + col + 1);
            *(float2*)(C + (size_t)row * N + col) =
                make_float2(c[0] + b0, c[1] + b1);
            *(float2*)(C + (size_t)(row + 8) * N + col) =
                make_float2(c[2] + b0, c[3] + b1);
        }
    }
}

// ---------------------------------------------------------------------------
// Windowed attention: online softmax, fp32 packed-f32x2 math, LDS.128 K/V.
// One CTA per (window, head), 128 threads, thread = query row. smem = K+V.
// Output written as tf32-rounded fp32 (ready for GEMM3).
// ---------------------------------------------------------------------------
__device__ __forceinline__ unsigned long long pk2(float lo, float hi) {
    unsigned long long r;
    asm("mov.b64 %0, {%1, %2};" : "=l"(r) : "f"(lo), "f"(hi));
    return r;
}
__device__ __forceinline__ void upk2(float& lo, float& hi, unsigned long long v) {
    asm("mov.b64 {%0, %1}, %2;" : "=f"(lo), "=f"(hi) : "l"(v));
}
__device__ __forceinline__ void ffma2(unsigned long long& c,
                                      unsigned long long a,
                                      unsigned long long b) {
    asm("fma.rn.f32x2 %0, %1, %2, %0;" : "+l"(c) : "l"(a), "l"(b));
}
__device__ __forceinline__ void fmul2(unsigned long long& c,
                                      unsigned long long a) {
    asm("mul.rn.f32x2 %0, %0, %1;" : "+l"(c) : "l"(a));
}

#define ATTN_SMEM ((8192 + 8192) * 4)

__global__ __launch_bounds__(128)
void attn_kernel(const float* __restrict__ qkv, float* __restrict__ att)
{
    extern __shared__ float sm[];
    float* Ks = sm;               // [128][64]
    float* Vs = sm + 8192;        // [128][64]

    const int w    = blockIdx.x;
    const int hd_i = blockIdx.y;
    const int tid  = threadIdx.x;

    const size_t base = (size_t)w * WIN * QKVDIM;
    const float* Kg = qkv + base + HDIM     + hd_i * HD;
    const float* Vg = qkv + base + 2 * HDIM + hd_i * HD;

    for (int idx = tid; idx < WIN * HD; idx += 128) {
        int row = idx >> 6, d = idx & 63;
        Ks[idx] = Kg[(size_t)row * QKVDIM + d];
        Vs[idx] = Vg[(size_t)row * QKVDIM + d];
    }

    const float4* Qg = (const float4*)(qkv + base + (size_t)tid * QKVDIM + hd_i * HD);
    unsigned long long q2[32];
#pragma unroll
    for (int i = 0; i < 16; ++i) {
        float4 v = Qg[i];
        q2[2*i]   = pk2(v.x, v.y);
        q2[2*i+1] = pk2(v.z, v.w);
    }
    __syncthreads();

    const ulonglong2* K4 = (const ulonglong2*)Ks;   // 16 per key row
    const ulonglong2* V4 = (const ulonglong2*)Vs;

    float m = -1e30f, l = 0.f;
    unsigned long long o2[32];
#pragma unroll
    for (int d = 0; d < 32; ++d) o2[d] = 0ull;

    for (int c = 0; c < 8; ++c) {             // 8 chunks of 16 keys
        float s[16];
#pragma unroll
        for (int jj = 0; jj < 16; ++jj) {
            const int j = c * 16 + jj;
            unsigned long long a0 = 0, a1 = 0, a2 = 0, a3 = 0;
            const ulonglong2* kj = K4 + j * 16;
#pragma unroll
            for (int d2 = 0; d2 < 16; d2 += 2) {
                ulonglong2 k0 = kj[d2];
                ulonglong2 k1 = kj[d2 + 1];
                ffma2(a0, q2[2*d2+0], k0.x);
                ffma2(a1, q2[2*d2+1], k0.y);
                ffma2(a2, q2[2*d2+2], k1.x);
                ffma2(a3, q2[2*d2+3], k1.y);
            }
            float lo, hi, ss;
            upk2(lo, hi, a0); ss  = lo + hi;
            upk2(lo, hi, a1); ss += lo + hi;
            upk2(lo, hi, a2); ss += lo + hi;
            upk2(lo, hi, a3); ss += lo + hi;
            s[jj] = ss * 0.125f;
        }
        float cm = s[0];
#pragma unroll
        for (int jj = 1; jj < 16; ++jj) cm = fmaxf(cm, s[jj]);
        const float nm = fmaxf(m, cm);
        const float sc = __expf(m - nm);
        m = nm;
        l *= sc;
        const unsigned long long sc2 = pk2(sc, sc);
#pragma unroll
        for (int d = 0; d < 32; ++d) fmul2(o2[d], sc2);
#pragma unroll
        for (int jj = 0; jj < 16; ++jj) {
            const float p = __expf(s[jj] - nm);
            l += p;
            const unsigned long long p2 = pk2(p, p);
            const ulonglong2* vj = V4 + (c * 16 + jj) * 16;
#pragma unroll
            for (int d2 = 0; d2 < 16; ++d2) {
                ulonglong2 vv = vj[d2];
                ffma2(o2[2*d2],   p2, vv.x);
                ffma2(o2[2*d2+1], p2, vv.y);
            }
        }
    }

    const float inv = 1.0f / l;
    float* Og = att + (size_t)(w * WIN + tid) * HDIM + hd_i * HD;
#pragma unroll
    for (int d = 0; d < 16; ++d) {
        float l0, h0, l1, h1;
        upk2(l0, h0, o2[2*d]);
        upk2(l1, h1, o2[2*d+1]);
        *(float4*)(Og + d * 4) = make_float4(
            rna_tf32(l0 * inv), rna_tf32(h0 * inv),
            rna_tf32(l1 * inv), rna_tf32(h1 * inv));
    }
}

// ---------------------------------------------------------------------------
extern "C" void kernel_launch(void* const* d_in, const int* in_sizes, int n_in,
                              void* d_out, int out_size)
{
    (void)in_sizes; (void)n_in; (void)out_size;
    const float* x     = (const float*)d_in[0];
    const float* w_in  = (const float*)d_in[1];
    const float* b_in  = (const float*)d_in[2];
    const float* w_out = (const float*)d_in[3];
    const float* b_out = (const float*)d_in[4];
    float* out = (float*)d_out;

    float *qkv, *xr, *wir, *wor, *att;
    cudaGetSymbolAddress((void**)&qkv, g_qkv);
    cudaGetSymbolAddress((void**)&xr,  g_xr);
    cudaGetSymbolAddress((void**)&wir, g_wir);
    cudaGetSymbolAddress((void**)&wor, g_wor);
    cudaGetSymbolAddress((void**)&att, g_att);

    cudaFuncSetAttribute(gemm_tf32,
                         cudaFuncAttributeMaxDynamicSharedMemorySize, GEMM_SMEM);
    cudaFuncSetAttribute(attn_kernel,
                         cudaFuncAttributeMaxDynamicSharedMemorySize, ATTN_SMEM);

    // round fp32 inputs to tf32 (rna)
    round_tf32<<<(M_TOK  * HDIM) / 1024, 256>>>((const float4*)x,     (float4*)xr);
    round_tf32<<<(QKVDIM * HDIM) / 1024, 256>>>((const float4*)w_in,  (float4*)wir);
    round_tf32<<<(HDIM   * HDIM) / 1024, 256>>>((const float4*)w_out, (float4*)wor);

    // Stage 1: QKV projection
    gemm_tf32<<<dim3(M_TOK / 128, QKVDIM / 256), 256, GEMM_SMEM>>>(
        xr, wir, b_in, qkv, QKVDIM);

    // Stage 2: windowed attention (online softmax, emits tf32-rounded fp32)
    attn_kernel<<<dim3(NWIN, NHEAD), 128, ATTN_SMEM>>>(qkv, att);

    // Stage 3: output projection
    gemm_tf32<<<dim3(M_TOK / 128, HDIM / 256), 256, GEMM_SMEM>>>(
        att, wor, b_out, out, HDIM);
}

// round 13
// speedup vs baseline: 1.0009x; 1.0009x over previous
#include <cuda_runtime.h>
#include <cuda_bf16.h>
#include <cstdint>

// ---------------------------------------------------------------------------
// LocalWindowTransformer on sm_103 (mma.sync tf32 path).
//   GEMM1: qkv = x @ Win^T + b_in   [16384 x 3072], K=1024
//   attn : per (window, head) online-softmax(qk^T/8)v  (fp32 FFMA2, LDS.128)
//   GEMM3: out = att @ Wout^T + b_out [16384 x 1024], K=1024
// tf32 single-product GEMM (mma.sync.m16n8k8, fp32 accum), inputs rna-rounded.
// R12: CTA 128x256, warp tile 64x64 (8 warps, 1 CTA/SM) -> LDS/MMA ratio 1.5x
//      down, tensor pipe becomes the sole binding resource.
// ---------------------------------------------------------------------------

#define M_TOK   16384
#define HDIM    1024
#define QKVDIM  3072
#define NHEAD   16
#define HD      64
#define WIN     128
#define NWIN    128

// ---- device scratch (no cudaMalloc allowed) --------------------------------
__device__ float g_qkv [(size_t)M_TOK * QKVDIM];    // 192 MiB
__device__ float g_xr  [(size_t)M_TOK * HDIM];      // 64 MiB (tf32-rounded x)
__device__ float g_wir [(size_t)QKVDIM * HDIM];     // 12 MiB
__device__ float g_wor [(size_t)HDIM * HDIM];       // 4 MiB
__device__ float g_att [(size_t)M_TOK * HDIM];      // 64 MiB (rounded attn out)

// ---- helpers ---------------------------------------------------------------
__device__ __forceinline__ uint32_t smem_u32(const void* p) {
    uint32_t a;
    asm("{ .reg .u64 t; cvta.to.shared.u64 t, %1; cvt.u32.u64 %0, t; }"
        : "=r"(a) : "l"(p));
    return a;
}
__device__ __forceinline__ void cp16(uint32_t dst, const void* src) {
    asm volatile("cp.async.cg.shared.global [%0], [%1], 16;"
                 :: "r"(dst), "l"(src));
}
__device__ __forceinline__ float rna_tf32(float v) {
    uint32_t r;
    asm("cvt.rna.tf32.f32 %0, %1;" : "=r"(r) : "f"(v));
    return __uint_as_float(r);
}

#define LDSM4(r, a) \
    asm volatile("ldmatrix.sync.aligned.m8n8.x4.shared.b16 {%0,%1,%2,%3}, [%4];" \
                 : "=r"((r)[0]), "=r"((r)[1]), "=r"((r)[2]), "=r"((r)[3]) \
                 : "r"(a))

#define MMAT(c, a, b0, b1) \
    asm volatile("mma.sync.aligned.m16n8k8.row.col.f32.tf32.tf32.f32 " \
                 "{%0,%1,%2,%3}, {%4,%5,%6,%7}, {%8,%9}, {%0,%1,%2,%3};" \
                 : "+f"((c)[0]), "+f"((c)[1]), "+f"((c)[2]), "+f"((c)[3]) \
                 : "r"((a)[0]), "r"((a)[1]), "r"((a)[2]), "r"((a)[3]), \
                   "r"(b0), "r"(b1))

// ---------------------------------------------------------------------------
// round fp32 -> tf32 (rna) elementwise. 1 thread = 4 values.
// ---------------------------------------------------------------------------
__global__ __launch_bounds__(256)
void round_tf32(const float4* __restrict__ src, float4* __restrict__ dst)
{
    int u = blockIdx.x * 256 + threadIdx.x;
    float4 v = src[u];
    v.x = rna_tf32(v.x); v.y = rna_tf32(v.y);
    v.z = rna_tf32(v.z); v.w = rna_tf32(v.w);
    dst[u] = v;
}

// ---------------------------------------------------------------------------
// tf32 NT GEMM: C[M,N] = A[M,1024] * B[N,1024]^T + bias
// BM=128, BN=256, BK=32 (fp32). 256 threads (8 warps 2x4), warp tile 64x64.
// smem: A 128x128B + B 256x128B per stage, XOR swizzle, 2-stage cp.async.
// 1 CTA/SM (high regs). ldmatrix.b16 view of fp32 -> tf32 fragments.
// ---------------------------------------------------------------------------
#define OFF_B  16384
#define STAGE  49152
#define KT     32               /* 1024 / 32 */
#define GEMM_SMEM (2 * STAGE)   /* 98304 B */

__global__ __launch_bounds__(256, 1)
void gemm_tf32(const float* __restrict__ A, const float* __restrict__ B,
               const float* __restrict__ bias, float* __restrict__ C, int N)
{
    extern __shared__ char smem_raw[];
    const uint32_t sb = smem_u32(smem_raw);

    const int tid  = threadIdx.x;
    const int lane = tid & 31;
    const int wid  = tid >> 5;
    const int wm   = wid & 1;           // 0..1  (64-row halves of 128)
    const int wn   = wid >> 1;          // 0..3  (64-col quarters of 256)
    const int bm   = blockIdx.x;
    const int bn   = blockIdx.y;

    // --- loaders ---
    // A: 128 rows x 8 units(16B): thread -> row=tid>>1, units (tid&1)*4..+3
    const int arow = tid >> 1;
    const int ahu  = (tid & 1) * 4;
    const int arm  = arow & 7;
    uint32_t dA[4];
#pragma unroll
    for (int i = 0; i < 4; ++i)
        dA[i] = arow * 128 + (((ahu + i) ^ arm) << 4);
    const float* pA = A + (size_t)(bm * 128 + arow) * 1024 + ahu * 4;

    // B: 256 rows x 8 units: thread -> row=tid, all 8 units
    const int brow = tid;
    const int brm  = brow & 7;
    uint32_t dB[8];
#pragma unroll
    for (int i = 0; i < 8; ++i)
        dB[i] = OFF_B + brow * 128 + ((i ^ brm) << 4);
    const float* pB = B + (size_t)(bn * 256 + brow) * 1024;

    auto issue = [&](uint32_t st, int ko) {
#pragma unroll
        for (int i = 0; i < 4; ++i)
            cp16(st + dA[i], pA + ko + i * 4);
#pragma unroll
        for (int i = 0; i < 8; ++i)
            cp16(st + dB[i], pB + ko + i * 4);
    };

    // --- ldmatrix row precompute ---
    int rowA[4], rmA[4];
#pragma unroll
    for (int mt = 0; mt < 4; ++mt) {
        rowA[mt] = wm * 64 + mt * 16 + ((lane >> 3) & 1) * 8 + (lane & 7);
        rmA[mt]  = rowA[mt] & 7;
    }
    const int uaA = lane >> 4;
    int rowB[4], rmB[4];
#pragma unroll
    for (int p = 0; p < 4; ++p) {
        rowB[p] = wn * 64 + p * 16 + (lane >> 4) * 8 + (lane & 7);
        rmB[p]  = rowB[p] & 7;
    }
    const int uaB = (lane >> 3) & 1;

    float acc[4][8][4];
#pragma unroll
    for (int i = 0; i < 4; ++i)
#pragma unroll
        for (int j = 0; j < 8; ++j)
#pragma unroll
            for (int k = 0; k < 4; ++k) acc[i][j][k] = 0.f;

    issue(sb, 0);
    asm volatile("cp.async.commit_group;" ::: "memory");

    for (int t = 0; t < KT; ++t) {
        if (t + 1 < KT) {
            issue(sb + ((t + 1) & 1) * STAGE, (t + 1) * 32);
            asm volatile("cp.async.commit_group;" ::: "memory");
            asm volatile("cp.async.wait_group 1;" ::: "memory");
        } else {
            asm volatile("cp.async.wait_group 0;" ::: "memory");
        }
        __syncthreads();                    // stage t visible

        const uint32_t st = sb + (t & 1) * STAGE;
#pragma unroll
        for (int ks = 0; ks < 4; ++ks) {
            uint32_t af[4][4], bf[4][4];
#pragma unroll
            for (int mt = 0; mt < 4; ++mt) {
                const uint32_t ad = st + rowA[mt] * 128 +
                                    (((ks * 2 + uaA) ^ rmA[mt]) << 4);
                LDSM4(af[mt], ad);
            }
#pragma unroll
            for (int p = 0; p < 4; ++p) {
                const uint32_t bd = st + OFF_B + rowB[p] * 128 +
                                    (((ks * 2 + uaB) ^ rmB[p]) << 4);
                LDSM4(bf[p], bd);
            }
#pragma unroll
            for (int mt = 0; mt < 4; ++mt) {
#pragma unroll
                for (int nt = 0; nt < 8; ++nt) {
                    const int p = nt >> 1, s = (nt & 1) * 2;
                    MMAT(acc[mt][nt], af[mt], bf[p][s], bf[p][s + 1]);
                }
            }
        }
        __syncthreads();                    // done reading stage t slot
    }

    // --- epilogue: register frags -> GMEM with bias ---
#pragma unroll
    for (int mt = 0; mt < 4; ++mt) {
#pragma unroll
        for (int nt = 0; nt < 8; ++nt) {
            const float* c = acc[mt][nt];
            const int row = bm * 128 + wm * 64 + mt * 16 + (lane >> 2);
            const int col = bn * 256 + wn * 64 + nt * 8 + (lane & 3) * 2;
            const float b0 = __ldg(bias + col);
            const float b1 = __ldg(bias + col + 1);
            *(float2*)(C + (size_t)row * N + col) =
                make_float2(c[0] + b0, c[1] + b1);
            *(float2*)(C + (size_t)(row + 8) * N + col) =
                make_float2(c[2] + b0, c[3] + b1);
        }
    }
}

// ---------------------------------------------------------------------------
// Windowed attention: online softmax, fp32 packed-f32x2 math, LDS.128 K/V.
// One CTA per (window, head), 128 threads, thread = query row. smem = K+V.
// Output written as tf32-rounded fp32 (ready for GEMM3).
// ---------------------------------------------------------------------------
__device__ __forceinline__ unsigned long long pk2(float lo, float hi) {
    unsigned long long r;
    asm("mov.b64 %0, {%1, %2};" : "=l"(r) : "f"(lo), "f"(hi));
    return r;
}
__device__ __forceinline__ void upk2(float& lo, float& hi, unsigned long long v) {
    asm("mov.b64 {%0, %1}, %2;" : "=f"(lo), "=f"(hi) : "l"(v));
}
__device__ __forceinline__ void ffma2(unsigned long long& c,
                                      unsigned long long a,
                                      unsigned long long b) {
    asm("fma.rn.f32x2 %0, %1, %2, %0;" : "+l"(c) : "l"(a), "l"(b));
}
__device__ __forceinline__ void fmul2(unsigned long long& c,
                                      unsigned long long a) {
    asm("mul.rn.f32x2 %0, %0, %1;" : "+l"(c) : "l"(a));
}

#define ATTN_SMEM ((8192 + 8192) * 4)

__global__ __launch_bounds__(128)
void attn_kernel(const float* __restrict__ qkv, float* __restrict__ att)
{
    extern __shared__ float sm[];
    float* Ks = sm;               // [128][64]
    float* Vs = sm + 8192;        // [128][64]

    const int w    = blockIdx.x;
    const int hd_i = blockIdx.y;
    const int tid  = threadIdx.x;

    const size_t base = (size_t)w * WIN * QKVDIM;
    const float* Kg = qkv + base + HDIM     + hd_i * HD;
    const float* Vg = qkv + base + 2 * HDIM + hd_i * HD;

    for (int idx = tid; idx < WIN * HD; idx += 128) {
        int row = idx >> 6, d = idx & 63;
        Ks[idx] = Kg[(size_t)row * QKVDIM + d];
        Vs[idx] = Vg[(size_t)row * QKVDIM + d];
    }

    const float4* Qg = (const float4*)(qkv + base + (size_t)tid * QKVDIM + hd_i * HD);
    unsigned long long q2[32];
#pragma unroll
    for (int i = 0; i < 16; ++i) {
        float4 v = Qg[i];
        q2[2*i]   = pk2(v.x, v.y);
        q2[2*i+1] = pk2(v.z, v.w);
    }
    __syncthreads();

    const ulonglong2* K4 = (const ulonglong2*)Ks;   // 16 per key row
    const ulonglong2* V4 = (const ulonglong2*)Vs;

    float m = -1e30f, l = 0.f;
    unsigned long long o2[32];
#pragma unroll
    for (int d = 0; d < 32; ++d) o2[d] = 0ull;

    for (int c = 0; c < 8; ++c) {             // 8 chunks of 16 keys
        float s[16];
#pragma unroll
        for (int jj = 0; jj < 16; ++jj) {
            const int j = c * 16 + jj;
            unsigned long long a0 = 0, a1 = 0, a2 = 0, a3 = 0;
            const ulonglong2* kj = K4 + j * 16;
#pragma unroll
            for (int d2 = 0; d2 < 16; d2 += 2) {
                ulonglong2 k0 = kj[d2];
                ulonglong2 k1 = kj[d2 + 1];
                ffma2(a0, q2[2*d2+0], k0.x);
                ffma2(a1, q2[2*d2+1], k0.y);
                ffma2(a2, q2[2*d2+2], k1.x);
                ffma2(a3, q2[2*d2+3], k1.y);
            }
            float lo, hi, ss;
            upk2(lo, hi, a0); ss  = lo + hi;
            upk2(lo, hi, a1); ss += lo + hi;
            upk2(lo, hi, a2); ss += lo + hi;
            upk2(lo, hi, a3); ss += lo + hi;
            s[jj] = ss * 0.125f;
        }
        float cm = s[0];
#pragma unroll
        for (int jj = 1; jj < 16; ++jj) cm = fmaxf(cm, s[jj]);
        const float nm = fmaxf(m, cm);
        const float sc = __expf(m - nm);
        m = nm;
        l *= sc;
        const unsigned long long sc2 = pk2(sc, sc);
#pragma unroll
        for (int d = 0; d < 32; ++d) fmul2(o2[d], sc2);
#pragma unroll
        for (int jj = 0; jj < 16; ++jj) {
            const float p = __expf(s[jj] - nm);
            l += p;
            const unsigned long long p2 = pk2(p, p);
            const ulonglong2* vj = V4 + (c * 16 + jj) * 16;
#pragma unroll
            for (int d2 = 0; d2 < 16; ++d2) {
                ulonglong2 vv = vj[d2];
                ffma2(o2[2*d2],   p2, vv.x);
                ffma2(o2[2*d2+1], p2, vv.y);
            }
        }
    }

    const float inv = 1.0f / l;
    float* Og = att + (size_t)(w * WIN + tid) * HDIM + hd_i * HD;
#pragma unroll
    for (int d = 0; d < 16; ++d) {
        float l0, h0, l1, h1;
        upk2(l0, h0, o2[2*d]);
        upk2(l1, h1, o2[2*d+1]);
        *(float4*)(Og + d * 4) = make_float4(
            rna_tf32(l0 * inv), rna_tf32(h0 * inv),
            rna_tf32(l1 * inv), rna_tf32(h1 * inv));
    }
}

// ---------------------------------------------------------------------------
extern "C" void kernel_launch(void* const* d_in, const int* in_sizes, int n_in,
                              void* d_out, int out_size)
{
    (void)in_sizes; (void)n_in; (void)out_size;
    const float* x     = (const float*)d_in[0];
    const float* w_in  = (const float*)d_in[1];
    const float* b_in  = (const float*)d_in[2];
    const float* w_out = (const float*)d_in[3];
    const float* b_out = (const float*)d_in[4];
    float* out = (float*)d_out;

    float *qkv, *xr, *wir, *wor, *att;
    cudaGetSymbolAddress((void**)&qkv, g_qkv);
    cudaGetSymbolAddress((void**)&xr,  g_xr);
    cudaGetSymbolAddress((void**)&wir, g_wir);
    cudaGetSymbolAddress((void**)&wor, g_wor);
    cudaGetSymbolAddress((void**)&att, g_att);

    cudaFuncSetAttribute(gemm_tf32,
                         cudaFuncAttributeMaxDynamicSharedMemorySize, GEMM_SMEM);
    cudaFuncSetAttribute(attn_kernel,
                         cudaFuncAttributeMaxDynamicSharedMemorySize, ATTN_SMEM);

    // round fp32 inputs to tf32 (rna)
    round_tf32<<<(M_TOK  * HDIM) / 1024, 256>>>((const float4*)x,     (float4*)xr);
    round_tf32<<<(QKVDIM * HDIM) / 1024, 256>>>((const float4*)w_in,  (float4*)wir);
    round_tf32<<<(HDIM   * HDIM) / 1024, 256>>>((const float4*)w_out, (float4*)wor);

    // Stage 1: QKV projection
    gemm_tf32<<<dim3(M_TOK / 128, QKVDIM / 256), 256, GEMM_SMEM>>>(
        xr, wir, b_in, qkv, QKVDIM);

    // Stage 2: windowed attention (online softmax, emits tf32-rounded fp32)
    attn_kernel<<<dim3(NWIN, NHEAD), 128, ATTN_SMEM>>>(qkv, att);

    // Stage 3: output projection
    gemm_tf32<<<dim3(M_TOK / 128, HDIM / 256), 256, GEMM_SMEM>>>(
        att, wor, b_out, out, HDIM);
}

// round 14
// speedup vs baseline: 1.2780x; 1.2768x over previous
#include <cuda_runtime.h>
#include <cuda_bf16.h>
#include <cstdint>

// ---------------------------------------------------------------------------
// LocalWindowTransformer on sm_103 (mma.sync tf32 path).
//   GEMM1: qkv = x @ Win^T + b_in   [16384 x 3072], K=1024
//   attn : per (window, head) online-softmax(qk^T/8)v  (fp32 FFMA2)
//   GEMM3: out = att @ Wout^T + b_out [16384 x 1024], K=1024
// tf32 single-product GEMM (mma.sync.m16n8k8, fp32 accum), inputs rna-rounded.
// R14: GEMM = R11 verbatim (best measured: 2 CTAs/SM, BK=32, 2-stage).
//      Attention: LDS.128 K/V + 2-key-unrolled score loop (8 FFMA2 chains).
// ---------------------------------------------------------------------------

#define M_TOK   16384
#define HDIM    1024
#define QKVDIM  3072
#define NHEAD   16
#define HD      64
#define WIN     128
#define NWIN    128

// ---- device scratch (no cudaMalloc allowed) --------------------------------
__device__ float g_qkv [(size_t)M_TOK * QKVDIM];    // 192 MiB
__device__ float g_xr  [(size_t)M_TOK * HDIM];      // 64 MiB (tf32-rounded x)
__device__ float g_wir [(size_t)QKVDIM * HDIM];     // 12 MiB
__device__ float g_wor [(size_t)HDIM * HDIM];       // 4 MiB
__device__ float g_att [(size_t)M_TOK * HDIM];      // 64 MiB (rounded attn out)

// ---- helpers ---------------------------------------------------------------
__device__ __forceinline__ uint32_t smem_u32(const void* p) {
    uint32_t a;
    asm("{ .reg .u64 t; cvta.to.shared.u64 t, %1; cvt.u32.u64 %0, t; }"
        : "=r"(a) : "l"(p));
    return a;
}
__device__ __forceinline__ void cp16(uint32_t dst, const void* src) {
    asm volatile("cp.async.cg.shared.global [%0], [%1], 16;"
                 :: "r"(dst), "l"(src));
}
__device__ __forceinline__ float rna_tf32(float v) {
    uint32_t r;
    asm("cvt.rna.tf32.f32 %0, %1;" : "=r"(r) : "f"(v));
    return __uint_as_float(r);
}

#define LDSM4(r, a) \
    asm volatile("ldmatrix.sync.aligned.m8n8.x4.shared.b16 {%0,%1,%2,%3}, [%4];" \
                 : "=r"((r)[0]), "=r"((r)[1]), "=r"((r)[2]), "=r"((r)[3]) \
                 : "r"(a))

#define MMAT(c, a, b0, b1) \
    asm volatile("mma.sync.aligned.m16n8k8.row.col.f32.tf32.tf32.f32 " \
                 "{%0,%1,%2,%3}, {%4,%5,%6,%7}, {%8,%9}, {%0,%1,%2,%3};" \
                 : "+f"((c)[0]), "+f"((c)[1]), "+f"((c)[2]), "+f"((c)[3]) \
                 : "r"((a)[0]), "r"((a)[1]), "r"((a)[2]), "r"((a)[3]), \
                   "r"(b0), "r"(b1))

// ---------------------------------------------------------------------------
// round fp32 -> tf32 (rna) elementwise. 1 thread = 4 values.
// ---------------------------------------------------------------------------
__global__ __launch_bounds__(256)
void round_tf32(const float4* __restrict__ src, float4* __restrict__ dst)
{
    int u = blockIdx.x * 256 + threadIdx.x;
    float4 v = src[u];
    v.x = rna_tf32(v.x); v.y = rna_tf32(v.y);
    v.z = rna_tf32(v.z); v.w = rna_tf32(v.w);
    dst[u] = v;
}

// ---------------------------------------------------------------------------
// tf32 NT GEMM (R11 verbatim): C[M,N] = A[M,1024] * B[N,1024]^T + bias
// BM=BN=128, BK=32, 256 threads (8 warps 2x4), warp tile 64x32.
// XOR-swizzled smem, 2-stage cp.async, 2 CTAs/SM.
// ---------------------------------------------------------------------------
#define OFF_B  16384
#define STAGE  32768
#define KT     32               /* 1024 / 32 */
#define GEMM_SMEM (2 * STAGE)   /* 65536 B */

__global__ __launch_bounds__(256, 2)
void gemm_tf32(const float* __restrict__ A, const float* __restrict__ B,
               const float* __restrict__ bias, float* __restrict__ C, int N)
{
    extern __shared__ char smem_raw[];
    const uint32_t sb = smem_u32(smem_raw);

    const int tid  = threadIdx.x;
    const int lane = tid & 31;
    const int wid  = tid >> 5;
    const int wm   = wid & 1;           // 0..1  (64-row halves)
    const int wn   = wid >> 1;          // 0..3  (32-col quarters)
    const int bm   = blockIdx.x;
    const int bn   = blockIdx.y;

    // --- loader: thread -> row = tid>>1, 4 units of 16B ((tid&1)*4 ..+3) ---
    const int lrow = tid >> 1;
    const int lhu  = (tid & 1) * 4;
    const int lrm  = lrow & 7;
    uint32_t dstu[4];
#pragma unroll
    for (int i = 0; i < 4; ++i)
        dstu[i] = lrow * 128 + (((lhu + i) ^ lrm) << 4);

    const float* pA = A + (size_t)(bm * 128 + lrow) * 1024 + lhu * 4;
    const float* pB = B + (size_t)(bn * 128 + lrow) * 1024 + lhu * 4;

    auto issue = [&](uint32_t st, int ko) {
#pragma unroll
        for (int i = 0; i < 4; ++i) {
            cp16(st + dstu[i],         pA + ko + i * 4);
            cp16(st + OFF_B + dstu[i], pB + ko + i * 4);
        }
    };

    // --- ldmatrix row precompute ---
    int rowA[4], rmA[4];
#pragma unroll
    for (int mt = 0; mt < 4; ++mt) {
        rowA[mt] = wm * 64 + mt * 16 + ((lane >> 3) & 1) * 8 + (lane & 7);
        rmA[mt]  = rowA[mt] & 7;
    }
    const int uaA = lane >> 4;
    int rowB[2], rmB[2];
#pragma unroll
    for (int p = 0; p < 2; ++p) {
        rowB[p] = wn * 32 + p * 16 + (lane >> 4) * 8 + (lane & 7);
        rmB[p]  = rowB[p] & 7;
    }
    const int uaB = (lane >> 3) & 1;

    float acc[4][4][4];
#pragma unroll
    for (int i = 0; i < 4; ++i)
#pragma unroll
        for (int j = 0; j < 4; ++j)
#pragma unroll
            for (int k = 0; k < 4; ++k) acc[i][j][k] = 0.f;

    issue(sb, 0);
    asm volatile("cp.async.commit_group;" ::: "memory");

    for (int t = 0; t < KT; ++t) {
        if (t + 1 < KT) {
            issue(sb + ((t + 1) & 1) * STAGE, (t + 1) * 32);
            asm volatile("cp.async.commit_group;" ::: "memory");
            asm volatile("cp.async.wait_group 1;" ::: "memory");
        } else {
            asm volatile("cp.async.wait_group 0;" ::: "memory");
        }
        __syncthreads();                    // stage t visible

        const uint32_t st = sb + (t & 1) * STAGE;
#pragma unroll
        for (int ks = 0; ks < 4; ++ks) {
            uint32_t af[4][4], bf[2][4];
#pragma unroll
            for (int mt = 0; mt < 4; ++mt) {
                const uint32_t ad = st + rowA[mt] * 128 +
                                    (((ks * 2 + uaA) ^ rmA[mt]) << 4);
                LDSM4(af[mt], ad);
            }
#pragma unroll
            for (int p = 0; p < 2; ++p) {
                const uint32_t bd = st + OFF_B + rowB[p] * 128 +
                                    (((ks * 2 + uaB) ^ rmB[p]) << 4);
                LDSM4(bf[p], bd);
            }
#pragma unroll
            for (int mt = 0; mt < 4; ++mt) {
#pragma unroll
                for (int nt = 0; nt < 4; ++nt) {
                    const int p = nt >> 1, s = (nt & 1) * 2;
                    MMAT(acc[mt][nt], af[mt], bf[p][s], bf[p][s + 1]);
                }
            }
        }
        __syncthreads();                    // done reading stage t slot
    }

    // --- epilogue: register frags -> GMEM with bias ---
#pragma unroll
    for (int mt = 0; mt < 4; ++mt) {
#pragma unroll
        for (int nt = 0; nt < 4; ++nt) {
            const float* c = acc[mt][nt];
            const int row = bm * 128 + wm * 64 + mt * 16 + (lane >> 2);
            const int col = bn * 128 + wn * 32 + nt * 8 + (lane & 3) * 2;
            const float b0 = __ldg(bias + col);
            const float b1 = __ldg(bias + col + 1);
            *(float2*)(C + (size_t)row * N + col) =
                make_float2(c[0] + b0, c[1] + b1);
            *(float2*)(C + (size_t)(row + 8) * N + col) =
                make_float2(c[2] + b0, c[3] + b1);
        }
    }
}

// ---------------------------------------------------------------------------
// Windowed attention: online softmax, fp32 packed-f32x2 math.
// LDS.128 K/V loads; QK score loop unrolled over 2 keys (8 FFMA2 chains).
// One CTA per (window, head), 128 threads, thread = query row. smem = K+V.
// ---------------------------------------------------------------------------
__device__ __forceinline__ unsigned long long pk2(float lo, float hi) {
    unsigned long long r;
    asm("mov.b64 %0, {%1, %2};" : "=l"(r) : "f"(lo), "f"(hi));
    return r;
}
__device__ __forceinline__ void upk2(float& lo, float& hi, unsigned long long v) {
    asm("mov.b64 {%0, %1}, %2;" : "=f"(lo), "=f"(hi) : "l"(v));
}
__device__ __forceinline__ void ffma2(unsigned long long& c,
                                      unsigned long long a,
                                      unsigned long long b) {
    asm("fma.rn.f32x2 %0, %1, %2, %0;" : "+l"(c) : "l"(a), "l"(b));
}
__device__ __forceinline__ void fmul2(unsigned long long& c,
                                      unsigned long long a) {
    asm("mul.rn.f32x2 %0, %0, %1;" : "+l"(c) : "l"(a));
}

#define ATTN_SMEM ((8192 + 8192) * 4)

__global__ __launch_bounds__(128)
void attn_kernel(const float* __restrict__ qkv, float* __restrict__ att)
{
    extern __shared__ float sm[];
    float* Ks = sm;               // [128][64]
    float* Vs = sm + 8192;        // [128][64]

    const int w    = blockIdx.x;
    const int hd_i = blockIdx.y;
    const int tid  = threadIdx.x;

    const size_t base = (size_t)w * WIN * QKVDIM;
    const float* Kg = qkv + base + HDIM     + hd_i * HD;
    const float* Vg = qkv + base + 2 * HDIM + hd_i * HD;

    for (int idx = tid; idx < WIN * HD; idx += 128) {
        int row = idx >> 6, d = idx & 63;
        Ks[idx] = Kg[(size_t)row * QKVDIM + d];
        Vs[idx] = Vg[(size_t)row * QKVDIM + d];
    }

    const float4* Qg = (const float4*)(qkv + base + (size_t)tid * QKVDIM + hd_i * HD);
    unsigned long long q2[32];
#pragma unroll
    for (int i = 0; i < 16; ++i) {
        float4 v = Qg[i];
        q2[2*i]   = pk2(v.x, v.y);
        q2[2*i+1] = pk2(v.z, v.w);
    }
    __syncthreads();

    const ulonglong2* K4 = (const ulonglong2*)Ks;   // 16 per key row
    const ulonglong2* V4 = (const ulonglong2*)Vs;

    float m = -1e30f, l = 0.f;
    unsigned long long o2[32];
#pragma unroll
    for (int d = 0; d < 32; ++d) o2[d] = 0ull;

    for (int c = 0; c < 8; ++c) {             // 8 chunks of 16 keys
        float s[16];
#pragma unroll
        for (int jj = 0; jj < 16; jj += 2) {  // 2 keys at once -> 8 chains
            const ulonglong2* kj0 = K4 + (c * 16 + jj) * 16;
            const ulonglong2* kj1 = kj0 + 16;
            unsigned long long a0 = 0, a1 = 0, a2 = 0, a3 = 0;
            unsigned long long b0 = 0, b1 = 0, b2 = 0, b3 = 0;
#pragma unroll
            for (int d2 = 0; d2 < 16; d2 += 2) {
                ulonglong2 x0 = kj0[d2];
                ulonglong2 x1 = kj0[d2 + 1];
                ulonglong2 y0 = kj1[d2];
                ulonglong2 y1 = kj1[d2 + 1];
                ffma2(a0, q2[2*d2+0], x0.x);
                ffma2(a1, q2[2*d2+1], x0.y);
                ffma2(a2, q2[2*d2+2], x1.x);
                ffma2(a3, q2[2*d2+3], x1.y);
                ffma2(b0, q2[2*d2+0], y0.x);
                ffma2(b1, q2[2*d2+1], y0.y);
                ffma2(b2, q2[2*d2+2], y1.x);
                ffma2(b3, q2[2*d2+3], y1.y);
            }
            float lo, hi, sa, sb2;
            upk2(lo, hi, a0); sa  = lo + hi;
            upk2(lo, hi, a1); sa += lo + hi;
            upk2(lo, hi, a2); sa += lo + hi;
            upk2(lo, hi, a3); sa += lo + hi;
            upk2(lo, hi, b0); sb2  = lo + hi;
            upk2(lo, hi, b1); sb2 += lo + hi;
            upk2(lo, hi, b2); sb2 += lo + hi;
            upk2(lo, hi, b3); sb2 += lo + hi;
            s[jj]     = sa  * 0.125f;
            s[jj + 1] = sb2 * 0.125f;
        }
        float cm = s[0];
#pragma unroll
        for (int jj = 1; jj < 16; ++jj) cm = fmaxf(cm, s[jj]);
        const float nm = fmaxf(m, cm);
        const float sc = __expf(m - nm);
        m = nm;
        l *= sc;
        const unsigned long long sc2 = pk2(sc, sc);
#pragma unroll
        for (int d = 0; d < 32; ++d) fmul2(o2[d], sc2);
#pragma unroll
        for (int jj = 0; jj < 16; ++jj) {
            const float p = __expf(s[jj] - nm);
            l += p;
            const unsigned long long p2 = pk2(p, p);
            const ulonglong2* vj = V4 + (c * 16 + jj) * 16;
#pragma unroll
            for (int d2 = 0; d2 < 16; ++d2) {
                ulonglong2 vv = vj[d2];
                ffma2(o2[2*d2],   p2, vv.x);
                ffma2(o2[2*d2+1], p2, vv.y);
            }
        }
    }

    const float inv = 1.0f / l;
    float* Og = att + (size_t)(w * WIN + tid) * HDIM + hd_i * HD;
#pragma unroll
    for (int d = 0; d < 16; ++d) {
        float l0, h0, l1, h1;
        upk2(l0, h0, o2[2*d]);
        upk2(l1, h1, o2[2*d+1]);
        *(float4*)(Og + d * 4) = make_float4(
            rna_tf32(l0 * inv), rna_tf32(h0 * inv),
            rna_tf32(l1 * inv), rna_tf32(h1 * inv));
    }
}

// ---------------------------------------------------------------------------
extern "C" void kernel_launch(void* const* d_in, const int* in_sizes, int n_in,
                              void* d_out, int out_size)
{
    (void)in_sizes; (void)n_in; (void)out_size;
    const float* x     = (const float*)d_in[0];
    const float* w_in  = (const float*)d_in[1];
    const float* b_in  = (const float*)d_in[2];
    const float* w_out = (const float*)d_in[3];
    const float* b_out = (const float*)d_in[4];
    float* out = (float*)d_out;

    float *qkv, *xr, *wir, *wor, *att;
    cudaGetSymbolAddress((void**)&qkv, g_qkv);
    cudaGetSymbolAddress((void**)&xr,  g_xr);
    cudaGetSymbolAddress((void**)&wir, g_wir);
    cudaGetSymbolAddress((void**)&wor, g_wor);
    cudaGetSymbolAddress((void**)&att, g_att);

    cudaFuncSetAttribute(gemm_tf32,
                         cudaFuncAttributeMaxDynamicSharedMemorySize, GEMM_SMEM);
    cudaFuncSetAttribute(attn_kernel,
                         cudaFuncAttributeMaxDynamicSharedMemorySize, ATTN_SMEM);

    // round fp32 inputs to tf32 (rna)
    round_tf32<<<(M_TOK  * HDIM) / 1024, 256>>>((const float4*)x,     (float4*)xr);
    round_tf32<<<(QKVDIM * HDIM) / 1024, 256>>>((const float4*)w_in,  (float4*)wir);
    round_tf32<<<(HDIM   * HDIM) / 1024, 256>>>((const float4*)w_out, (float4*)wor);

    // Stage 1: QKV projection
    gemm_tf32<<<dim3(M_TOK / 128, QKVDIM / 128), 256, GEMM_SMEM>>>(
        xr, wir, b_in, qkv, QKVDIM);

    // Stage 2: windowed attention (online softmax, emits tf32-rounded fp32)
    attn_kernel<<<dim3(NWIN, NHEAD), 128, ATTN_SMEM>>>(qkv, att);

    // Stage 3: output projection
    gemm_tf32<<<dim3(M_TOK / 128, HDIM / 128), 256, GEMM_SMEM>>>(
        att, wor, b_out, out, HDIM);
}

// round 15
// speedup vs baseline: 1.5744x; 1.2319x over previous
#include <cuda_runtime.h>
#include <cuda_bf16.h>
#include <cstdint>

// ---------------------------------------------------------------------------
// LocalWindowTransformer on sm_103 (mma.sync tf32 path).
//   GEMM1: qkv = x @ Win^T + b_in   [16384 x 3072], K=1024
//   attn : per (window, head) flash softmax(qk^T/8)v — tf32 MMA QK and PV
//   GEMM3: out = att @ Wout^T + b_out [16384 x 1024], K=1024
// R15: attention moved to tensor cores (register-resident S blocks, online
//      softmax, acc->A-frag shuffles, V transposed in smem); GEMM mainloop
//      upgraded to 3-stage cp.async at 2 CTAs/SM (one barrier per K-tile).
// ---------------------------------------------------------------------------

#define M_TOK   16384
#define HDIM    1024
#define QKVDIM  3072
#define NHEAD   16
#define HD      64
#define WIN     128
#define NWIN    128

// ---- device scratch (no cudaMalloc allowed) --------------------------------
__device__ float g_qkv [(size_t)M_TOK * QKVDIM];    // 192 MiB
__device__ float g_xr  [(size_t)M_TOK * HDIM];      // tf32-rounded x
__device__ float g_wir [(size_t)QKVDIM * HDIM];
__device__ float g_wor [(size_t)HDIM * HDIM];
__device__ float g_att [(size_t)M_TOK * HDIM];      // rounded attn out

// ---- helpers ---------------------------------------------------------------
__device__ __forceinline__ uint32_t smem_u32(const void* p) {
    uint32_t a;
    asm("{ .reg .u64 t; cvta.to.shared.u64 t, %1; cvt.u32.u64 %0, t; }"
        : "=r"(a) : "l"(p));
    return a;
}
__device__ __forceinline__ void cp16(uint32_t dst, const void* src) {
    asm volatile("cp.async.cg.shared.global [%0], [%1], 16;"
                 :: "r"(dst), "l"(src));
}
__device__ __forceinline__ float rna_tf32(float v) {
    uint32_t r;
    asm("cvt.rna.tf32.f32 %0, %1;" : "=r"(r) : "f"(v));
    return __uint_as_float(r);
}

#define LDSM4(r, a) \
    asm volatile("ldmatrix.sync.aligned.m8n8.x4.shared.b16 {%0,%1,%2,%3}, [%4];" \
                 : "=r"((r)[0]), "=r"((r)[1]), "=r"((r)[2]), "=r"((r)[3]) \
                 : "r"(a))

#define MMAT(c, a, b0, b1) \
    asm volatile("mma.sync.aligned.m16n8k8.row.col.f32.tf32.tf32.f32 " \
                 "{%0,%1,%2,%3}, {%4,%5,%6,%7}, {%8,%9}, {%0,%1,%2,%3};" \
                 : "+f"((c)[0]), "+f"((c)[1]), "+f"((c)[2]), "+f"((c)[3]) \
                 : "r"((a)[0]), "r"((a)[1]), "r"((a)[2]), "r"((a)[3]), \
                   "r"(b0), "r"(b1))

// ---------------------------------------------------------------------------
// round fp32 -> tf32 (rna) elementwise. 1 thread = 4 values.
// ---------------------------------------------------------------------------
__global__ __launch_bounds__(256)
void round_tf32(const float4* __restrict__ src, float4* __restrict__ dst)
{
    int u = blockIdx.x * 256 + threadIdx.x;
    float4 v = src[u];
    v.x = rna_tf32(v.x); v.y = rna_tf32(v.y);
    v.z = rna_tf32(v.z); v.w = rna_tf32(v.w);
    dst[u] = v;
}

// ---------------------------------------------------------------------------
// tf32 NT GEMM: C[M,N] = A[M,1024] * B[N,1024]^T + bias
// BM=BN=128, BK=32, 256 threads (8 warps 2x4), warp tile 64x32.
// XOR-swizzled smem, 3-stage cp.async (one barrier per tile), 2 CTAs/SM.
// ---------------------------------------------------------------------------
#define OFF_B  16384
#define STAGE  32768
#define KT     32               /* 1024 / 32 */
#define GEMM_SMEM (3 * STAGE)   /* 98304 B */

__global__ __launch_bounds__(256, 2)
void gemm_tf32(const float* __restrict__ A, const float* __restrict__ B,
               const float* __restrict__ bias, float* __restrict__ C, int N)
{
    extern __shared__ char smem_raw[];
    const uint32_t sb = smem_u32(smem_raw);

    const int tid  = threadIdx.x;
    const int lane = tid & 31;
    const int wid  = tid >> 5;
    const int wm   = wid & 1;
    const int wn   = wid >> 1;
    const int bm   = blockIdx.x;
    const int bn   = blockIdx.y;

    const int lrow = tid >> 1;
    const int lhu  = (tid & 1) * 4;
    const int lrm  = lrow & 7;
    uint32_t dstu[4];
#pragma unroll
    for (int i = 0; i < 4; ++i)
        dstu[i] = lrow * 128 + (((lhu + i) ^ lrm) << 4);

    const float* pA = A + (size_t)(bm * 128 + lrow) * 1024 + lhu * 4;
    const float* pB = B + (size_t)(bn * 128 + lrow) * 1024 + lhu * 4;

    auto issue = [&](uint32_t st, int ko) {
#pragma unroll
        for (int i = 0; i < 4; ++i) {
            cp16(st + dstu[i],         pA + ko + i * 4);
            cp16(st + OFF_B + dstu[i], pB + ko + i * 4);
        }
    };

    int rowA[4], rmA[4];
#pragma unroll
    for (int mt = 0; mt < 4; ++mt) {
        rowA[mt] = wm * 64 + mt * 16 + ((lane >> 3) & 1) * 8 + (lane & 7);
        rmA[mt]  = rowA[mt] & 7;
    }
    const int uaA = lane >> 4;
    int rowB[2], rmB[2];
#pragma unroll
    for (int p = 0; p < 2; ++p) {
        rowB[p] = wn * 32 + p * 16 + (lane >> 4) * 8 + (lane & 7);
        rmB[p]  = rowB[p] & 7;
    }
    const int uaB = (lane >> 3) & 1;

    float acc[4][4][4];
#pragma unroll
    for (int i = 0; i < 4; ++i)
#pragma unroll
        for (int j = 0; j < 4; ++j)
#pragma unroll
            for (int k = 0; k < 4; ++k) acc[i][j][k] = 0.f;

    issue(sb, 0);
    asm volatile("cp.async.commit_group;" ::: "memory");
    issue(sb + STAGE, 32);
    asm volatile("cp.async.commit_group;" ::: "memory");

    int cs = 0, ws = 2;
    for (int t = 0; t < KT; ++t) {
        asm volatile("cp.async.wait_group 1;" ::: "memory");
        __syncthreads();                    // stage t visible; slot ws free

        if (t + 2 < KT)
            issue(sb + ws * STAGE, (t + 2) * 32);
        asm volatile("cp.async.commit_group;" ::: "memory");
        ws = (ws == 2) ? 0 : ws + 1;

        const uint32_t st = sb + cs * STAGE;
        cs = (cs == 2) ? 0 : cs + 1;
#pragma unroll
        for (int ks = 0; ks < 4; ++ks) {
            uint32_t af[4][4], bf[2][4];
#pragma unroll
            for (int mt = 0; mt < 4; ++mt) {
                const uint32_t ad = st + rowA[mt] * 128 +
                                    (((ks * 2 + uaA) ^ rmA[mt]) << 4);
                LDSM4(af[mt], ad);
            }
#pragma unroll
            for (int p = 0; p < 2; ++p) {
                const uint32_t bd = st + OFF_B + rowB[p] * 128 +
                                    (((ks * 2 + uaB) ^ rmB[p]) << 4);
                LDSM4(bf[p], bd);
            }
#pragma unroll
            for (int mt = 0; mt < 4; ++mt) {
#pragma unroll
                for (int nt = 0; nt < 4; ++nt) {
                    const int p = nt >> 1, s = (nt & 1) * 2;
                    MMAT(acc[mt][nt], af[mt], bf[p][s], bf[p][s + 1]);
                }
            }
        }
    }

#pragma unroll
    for (int mt = 0; mt < 4; ++mt) {
#pragma unroll
        for (int nt = 0; nt < 4; ++nt) {
            const float* c = acc[mt][nt];
            const int row = bm * 128 + wm * 64 + mt * 16 + (lane >> 2);
            const int col = bn * 128 + wn * 32 + nt * 8 + (lane & 3) * 2;
            const float b0 = __ldg(bias + col);
            const float b1 = __ldg(bias + col + 1);
            *(float2*)(C + (size_t)row * N + col) =
                make_float2(c[0] + b0, c[1] + b1);
            *(float2*)(C + (size_t)(row + 8) * N + col) =
                make_float2(c[2] + b0, c[3] + b1);
        }
    }
}

// ---------------------------------------------------------------------------
// MMA attention: one CTA per (window, head), 128 threads (4 warps),
// warp = 32 query rows. tf32 mma.sync for QK^T and PV; online softmax over
// 4 key-blocks of 32 keys held in registers.
// smem: Q[128x68f], K[128x68f] (272B rows: pad-17 units, ldmatrix
// conflict-free, no swizzle), Vt[64x132f] (V transposed, 528B rows).
// ---------------------------------------------------------------------------
#define ATTN_SMEM 103424

__global__ __launch_bounds__(128)
void attn_kernel(const float* __restrict__ qkv, float* __restrict__ att)
{
    extern __shared__ float sm[];
    float* Qs = sm;             // 128 x 68
    float* Ks = sm + 8704;      // 128 x 68
    float* Vt = sm + 17408;     // 64 x 132  (Vt[d][key])

    const int w    = blockIdx.x;
    const int h    = blockIdx.y;
    const int tid  = threadIdx.x;
    const int lane = tid & 31;
    const int wi   = tid >> 5;

    const size_t base = (size_t)w * WIN * QKVDIM + h * HD;

    // ---- fill smem (rna-rounded; Q pre-scaled by 1/sqrt(64)) ----
    {
        const float4* Qg = (const float4*)(qkv + base + (size_t)tid * QKVDIM);
        const float4* Kg = (const float4*)(qkv + base + (size_t)tid * QKVDIM + HDIM);
        const float4* Vg = (const float4*)(qkv + base + (size_t)tid * QKVDIM + 2 * HDIM);
        float* qr = Qs + tid * 68;
        float* kr = Ks + tid * 68;
#pragma unroll
        for (int i = 0; i < 16; ++i) {
            float4 q = Qg[i], k = Kg[i], v = Vg[i];
            qr[4*i+0] = rna_tf32(q.x * 0.125f);
            qr[4*i+1] = rna_tf32(q.y * 0.125f);
            qr[4*i+2] = rna_tf32(q.z * 0.125f);
            qr[4*i+3] = rna_tf32(q.w * 0.125f);
            kr[4*i+0] = rna_tf32(k.x);
            kr[4*i+1] = rna_tf32(k.y);
            kr[4*i+2] = rna_tf32(k.z);
            kr[4*i+3] = rna_tf32(k.w);
            Vt[(4*i+0) * 132 + tid] = rna_tf32(v.x);
            Vt[(4*i+1) * 132 + tid] = rna_tf32(v.y);
            Vt[(4*i+2) * 132 + tid] = rna_tf32(v.z);
            Vt[(4*i+3) * 132 + tid] = rna_tf32(v.w);
        }
    }
    __syncthreads();

    const uint32_t qb = smem_u32(Qs);
    const uint32_t kbs = smem_u32(Ks);
    const uint32_t vb = smem_u32(Vt);

    // fragment addressing (mirrors the verified GEMM patterns, unswizzled)
    int rowA[2];
    rowA[0] = wi * 32 + ((lane >> 3) & 1) * 8 + (lane & 7);
    rowA[1] = rowA[0] + 16;
    const int uaA = lane >> 4;
    int rowK[2];
    rowK[0] = (lane >> 4) * 8 + (lane & 7);
    rowK[1] = rowK[0] + 16;
    const int uaB = (lane >> 3) & 1;
    int rowV[4];
#pragma unroll
    for (int p = 0; p < 4; ++p)
        rowV[p] = p * 16 + (lane >> 4) * 8 + (lane & 7);

    float o[2][8][4];
#pragma unroll
    for (int mt = 0; mt < 2; ++mt)
#pragma unroll
        for (int nt = 0; nt < 8; ++nt)
#pragma unroll
            for (int k = 0; k < 4; ++k) o[mt][nt][k] = 0.f;
    float mrow[2][2] = {{-1e30f, -1e30f}, {-1e30f, -1e30f}};
    float lrow[2][2] = {{0.f, 0.f}, {0.f, 0.f}};

    const int  srcl = (lane & 28) | ((lane >> 1) & 1);
    const int  srch = srcl + 2;
    const bool oddl = (lane & 1) != 0;

    for (int kb = 0; kb < 4; ++kb) {
        // ---- S = Q K^T (32-key block) ----
        float sacc[2][4][4];
#pragma unroll
        for (int mt = 0; mt < 2; ++mt)
#pragma unroll
            for (int nt = 0; nt < 4; ++nt)
#pragma unroll
                for (int k = 0; k < 4; ++k) sacc[mt][nt][k] = 0.f;
#pragma unroll
        for (int ks = 0; ks < 8; ++ks) {
            uint32_t af[2][4], bf[2][4];
#pragma unroll
            for (int mt = 0; mt < 2; ++mt)
                LDSM4(af[mt], qb + rowA[mt] * 272 + (ks * 2 + uaA) * 16);
#pragma unroll
            for (int p = 0; p < 2; ++p)
                LDSM4(bf[p], kbs + (kb * 32 + rowK[p]) * 272 + (ks * 2 + uaB) * 16);
#pragma unroll
            for (int mt = 0; mt < 2; ++mt)
#pragma unroll
                for (int nt = 0; nt < 4; ++nt) {
                    const int p = nt >> 1, s = (nt & 1) * 2;
                    MMAT(sacc[mt][nt], af[mt], bf[p][s], bf[p][s + 1]);
                }
        }

        // ---- online softmax update ----
        float sc[2][2];
#pragma unroll
        for (int mt = 0; mt < 2; ++mt)
#pragma unroll
            for (int rh = 0; rh < 2; ++rh) {
                float bm = sacc[mt][0][rh * 2];
#pragma unroll
                for (int nt = 0; nt < 4; ++nt) {
                    bm = fmaxf(bm, sacc[mt][nt][rh * 2]);
                    bm = fmaxf(bm, sacc[mt][nt][rh * 2 + 1]);
                }
                bm = fmaxf(bm, __shfl_xor_sync(0xFFFFFFFFu, bm, 1));
                bm = fmaxf(bm, __shfl_xor_sync(0xFFFFFFFFu, bm, 2));
                const float mn = fmaxf(mrow[mt][rh], bm);
                sc[mt][rh] = __expf(mrow[mt][rh] - mn);
                mrow[mt][rh] = mn;
            }
#pragma unroll
        for (int mt = 0; mt < 2; ++mt)
#pragma unroll
            for (int rh = 0; rh < 2; ++rh) {
                float ps = 0.f;
#pragma unroll
                for (int nt = 0; nt < 4; ++nt) {
                    float p0 = rna_tf32(__expf(sacc[mt][nt][rh * 2]     - mrow[mt][rh]));
                    float p1 = rna_tf32(__expf(sacc[mt][nt][rh * 2 + 1] - mrow[mt][rh]));
                    sacc[mt][nt][rh * 2]     = p0;
                    sacc[mt][nt][rh * 2 + 1] = p1;
                    ps += p0 + p1;
                }
                ps += __shfl_xor_sync(0xFFFFFFFFu, ps, 1);
                ps += __shfl_xor_sync(0xFFFFFFFFu, ps, 2);
                lrow[mt][rh] = lrow[mt][rh] * sc[mt][rh] + ps;
            }
#pragma unroll
        for (int mt = 0; mt < 2; ++mt)
#pragma unroll
            for (int nt = 0; nt < 8; ++nt) {
                o[mt][nt][0] *= sc[mt][0];
                o[mt][nt][1] *= sc[mt][0];
                o[mt][nt][2] *= sc[mt][1];
                o[mt][nt][3] *= sc[mt][1];
            }

        // ---- acc layout -> A-fragment layout for P (shfl within quads) ----
        uint32_t pa[2][4][4];
#pragma unroll
        for (int mt = 0; mt < 2; ++mt)
#pragma unroll
            for (int kt = 0; kt < 4; ++kt) {
                float t0, t1;
                t0 = __shfl_sync(0xFFFFFFFFu, sacc[mt][kt][0], srcl);
                t1 = __shfl_sync(0xFFFFFFFFu, sacc[mt][kt][1], srcl);
                pa[mt][kt][0] = __float_as_uint(oddl ? t1 : t0);
                t0 = __shfl_sync(0xFFFFFFFFu, sacc[mt][kt][2], srcl);
                t1 = __shfl_sync(0xFFFFFFFFu, sacc[mt][kt][3], srcl);
                pa[mt][kt][1] = __float_as_uint(oddl ? t1 : t0);
                t0 = __shfl_sync(0xFFFFFFFFu, sacc[mt][kt][0], srch);
                t1 = __shfl_sync(0xFFFFFFFFu, sacc[mt][kt][1], srch);
                pa[mt][kt][2] = __float_as_uint(oddl ? t1 : t0);
                t0 = __shfl_sync(0xFFFFFFFFu, sacc[mt][kt][2], srch);
                t1 = __shfl_sync(0xFFFFFFFFu, sacc[mt][kt][3], srch);
                pa[mt][kt][3] = __float_as_uint(oddl ? t1 : t0);
            }

        // ---- O += P V  (B operand from transposed V) ----
#pragma unroll
        for (int kpv = 0; kpv < 4; ++kpv) {
            uint32_t bv[4][4];
#pragma unroll
            for (int p = 0; p < 4; ++p)
                LDSM4(bv[p], vb + rowV[p] * 528 + (kb * 8 + kpv * 2 + uaB) * 16);
#pragma unroll
            for (int mt = 0; mt < 2; ++mt)
#pragma unroll
                for (int nt = 0; nt < 8; ++nt) {
                    const int p = nt >> 1, s = (nt & 1) * 2;
                    MMAT(o[mt][nt], pa[mt][kpv], bv[p][s], bv[p][s + 1]);
                }
        }
    }

    // ---- normalize + store (rna for GEMM3) ----
    float inv[2][2];
#pragma unroll
    for (int mt = 0; mt < 2; ++mt) {
        inv[mt][0] = 1.0f / lrow[mt][0];
        inv[mt][1] = 1.0f / lrow[mt][1];
    }
#pragma unroll
    for (int mt = 0; mt < 2; ++mt) {
        const int r0 = w * 128 + wi * 32 + mt * 16 + (lane >> 2);
#pragma unroll
        for (int nt = 0; nt < 8; ++nt) {
            const int col = h * 64 + nt * 8 + (lane & 3) * 2;
            *(float2*)(att + (size_t)r0 * HDIM + col) = make_float2(
                rna_tf32(o[mt][nt][0] * inv[mt][0]),
                rna_tf32(o[mt][nt][1] * inv[mt][0]));
            *(float2*)(att + (size_t)(r0 + 8) * HDIM + col) = make_float2(
                rna_tf32(o[mt][nt][2] * inv[mt][1]),
                rna_tf32(o[mt][nt][3] * inv[mt][1]));
        }
    }
}

// ---------------------------------------------------------------------------
extern "C" void kernel_launch(void* const* d_in, const int* in_sizes, int n_in,
                              void* d_out, int out_size)
{
    (void)in_sizes; (void)n_in; (void)out_size;
    const float* x     = (const float*)d_in[0];
    const float* w_in  = (const float*)d_in[1];
    const float* b_in  = (const float*)d_in[2];
    const float* w_out = (const float*)d_in[3];
    const float* b_out = (const float*)d_in[4];
    float* out = (float*)d_out;

    float *qkv, *xr, *wir, *wor, *att;
    cudaGetSymbolAddress((void**)&qkv, g_qkv);
    cudaGetSymbolAddress((void**)&xr,  g_xr);
    cudaGetSymbolAddress((void**)&wir, g_wir);
    cudaGetSymbolAddress((void**)&wor, g_wor);
    cudaGetSymbolAddress((void**)&att, g_att);

    cudaFuncSetAttribute(gemm_tf32,
                         cudaFuncAttributeMaxDynamicSharedMemorySize, GEMM_SMEM);
    cudaFuncSetAttribute(attn_kernel,
                         cudaFuncAttributeMaxDynamicSharedMemorySize, ATTN_SMEM);

    // round fp32 inputs to tf32 (rna)
    round_tf32<<<(M_TOK  * HDIM) / 1024, 256>>>((const float4*)x,     (float4*)xr);
    round_tf32<<<(QKVDIM * HDIM) / 1024, 256>>>((const float4*)w_in,  (float4*)wir);
    round_tf32<<<(HDIM   * HDIM) / 1024, 256>>>((const float4*)w_out, (float4*)wor);

    // Stage 1: QKV projection
    gemm_tf32<<<dim3(M_TOK / 128, QKVDIM / 128), 256, GEMM_SMEM>>>(
        xr, wir, b_in, qkv, QKVDIM);

    // Stage 2: windowed attention (tf32 MMA, flash softmax)
    attn_kernel<<<dim3(NWIN, NHEAD), 128, ATTN_SMEM>>>(qkv, att);

    // Stage 3: output projection
    gemm_tf32<<<dim3(M_TOK / 128, HDIM / 128), 256, GEMM_SMEM>>>(
        att, wor, b_out, out, HDIM);
}

// round 16
// speedup vs baseline: 2.2591x; 1.4349x over previous
#include <cuda_runtime.h>
#include <cuda_fp16.h>
#include <cuda_bf16.h>
#include <cstdint>

// ---------------------------------------------------------------------------
// LocalWindowTransformer on sm_103.
//   GEMM1: qkv = x @ Win^T + b_in   [16384 x 3072], K=1024   (fp16 HMMA)
//   attn : per (window, head) flash softmax(qk^T/8)v          (tf32 MMA)
//   GEMM3: out = att @ Wout^T + b_out [16384 x 1024], K=1024  (fp16 HMMA)
// R16: GEMMs moved from tf32 m16n8k8 to fp16 m16n8k16 single product --
//      same 11-bit mantissa, K=16 per instruction, half the operand bytes:
//      MMA count, LDS traffic and cp.async traffic all halve per unit work.
//      Attention unchanged internally (tf32), now emits fp16 att directly.
// ---------------------------------------------------------------------------

#define M_TOK   16384
#define HDIM    1024
#define QKVDIM  3072
#define NHEAD   16
#define HD      64
#define WIN     128
#define NWIN    128

// ---- device scratch (no cudaMalloc allowed) --------------------------------
__device__ float  g_qkv [(size_t)M_TOK * QKVDIM];    // 192 MiB fp32
__device__ __half g_xh  [(size_t)M_TOK * HDIM];      // 32 MiB
__device__ __half g_wih [(size_t)QKVDIM * HDIM];     // 6 MiB
__device__ __half g_woh [(size_t)HDIM * HDIM];       // 2 MiB
__device__ __half g_att [(size_t)M_TOK * HDIM];      // 32 MiB (attn out, fp16)

// ---- helpers ---------------------------------------------------------------
__device__ __forceinline__ uint32_t smem_u32(const void* p) {
    uint32_t a;
    asm("{ .reg .u64 t; cvta.to.shared.u64 t, %1; cvt.u32.u64 %0, t; }"
        : "=r"(a) : "l"(p));
    return a;
}
__device__ __forceinline__ void cp16(uint32_t dst, const void* src) {
    asm volatile("cp.async.cg.shared.global [%0], [%1], 16;"
                 :: "r"(dst), "l"(src));
}
__device__ __forceinline__ float rna_tf32(float v) {
    uint32_t r;
    asm("cvt.rna.tf32.f32 %0, %1;" : "=r"(r) : "f"(v));
    return __uint_as_float(r);
}

#define LDSM4(r, a) \
    asm volatile("ldmatrix.sync.aligned.m8n8.x4.shared.b16 {%0,%1,%2,%3}, [%4];" \
                 : "=r"((r)[0]), "=r"((r)[1]), "=r"((r)[2]), "=r"((r)[3]) \
                 : "r"(a))

#define MMAT(c, a, b0, b1) \
    asm volatile("mma.sync.aligned.m16n8k8.row.col.f32.tf32.tf32.f32 " \
                 "{%0,%1,%2,%3}, {%4,%5,%6,%7}, {%8,%9}, {%0,%1,%2,%3};" \
                 : "+f"((c)[0]), "+f"((c)[1]), "+f"((c)[2]), "+f"((c)[3]) \
                 : "r"((a)[0]), "r"((a)[1]), "r"((a)[2]), "r"((a)[3]), \
                   "r"(b0), "r"(b1))

#define MMAH(c, a, b0, b1) \
    asm volatile("mma.sync.aligned.m16n8k16.row.col.f32.f16.f16.f32 " \
                 "{%0,%1,%2,%3}, {%4,%5,%6,%7}, {%8,%9}, {%0,%1,%2,%3};" \
                 : "+f"((c)[0]), "+f"((c)[1]), "+f"((c)[2]), "+f"((c)[3]) \
                 : "r"((a)[0]), "r"((a)[1]), "r"((a)[2]), "r"((a)[3]), \
                   "r"(b0), "r"(b1))

// ---------------------------------------------------------------------------
// convert fp32 -> fp16 (rn). 1 thread = 8 values (one uint4 out).
// ---------------------------------------------------------------------------
__global__ __launch_bounds__(256)
void to_half(const float4* __restrict__ src, uint4* __restrict__ dst)
{
    int u = blockIdx.x * 256 + threadIdx.x;
    float4 a = src[2 * u], b = src[2 * u + 1];
    __half2 h0 = __floats2half2_rn(a.x, a.y);
    __half2 h1 = __floats2half2_rn(a.z, a.w);
    __half2 h2 = __floats2half2_rn(b.x, b.y);
    __half2 h3 = __floats2half2_rn(b.z, b.w);
    uint4 o;
    o.x = *(uint32_t*)&h0; o.y = *(uint32_t*)&h1;
    o.z = *(uint32_t*)&h2; o.w = *(uint32_t*)&h3;
    dst[u] = o;
}

// ---------------------------------------------------------------------------
// fp16 NT GEMM: C[M,N] = A[M,1024] * B[N,1024]^T + bias (fp32 accum)
// BM=BN=128, BK=64 (fp16, 128B rows), 256 threads (8 warps 2x4),
// warp tile 64x32, XOR-swizzled smem, 3-stage cp.async, 2 CTAs/SM.
// Fragment addressing = R3's verified bf16 pattern + R11's swizzle.
// ---------------------------------------------------------------------------
#define OFF_B  16384
#define STAGE  32768
#define KTH    16               /* 1024 / 64 */
#define GEMM_SMEM (3 * STAGE)   /* 98304 B */

__global__ __launch_bounds__(256, 2)
void gemm_f16(const __half* __restrict__ A, const __half* __restrict__ B,
              const float* __restrict__ bias, float* __restrict__ C, int N)
{
    extern __shared__ char smem_raw[];
    const uint32_t sb = smem_u32(smem_raw);

    const int tid  = threadIdx.x;
    const int lane = tid & 31;
    const int wid  = tid >> 5;
    const int wm   = wid & 1;           // 0..1  (64-row halves)
    const int wn   = wid >> 1;          // 0..3  (32-col quarters)
    const int bm   = blockIdx.x;
    const int bn   = blockIdx.y;

    // --- loader: thread -> row = tid>>1, 4 units of 16B ((tid&1)*4 ..+3) ---
    const int lrow = tid >> 1;
    const int lhu  = (tid & 1) * 4;
    const int lrm  = lrow & 7;
    uint32_t dstu[4];
#pragma unroll
    for (int i = 0; i < 4; ++i)
        dstu[i] = lrow * 128 + (((lhu + i) ^ lrm) << 4);

    const __half* pA = A + (size_t)(bm * 128 + lrow) * 1024 + lhu * 8;
    const __half* pB = B + (size_t)(bn * 128 + lrow) * 1024 + lhu * 8;

    auto issue = [&](uint32_t st, int ko) {
#pragma unroll
        for (int i = 0; i < 4; ++i) {
            cp16(st + dstu[i],         pA + ko + i * 8);
            cp16(st + OFF_B + dstu[i], pB + ko + i * 8);
        }
    };

    // --- ldmatrix addressing (R3-verified b16 pattern) ---
    int rowA[4], rmA[4];
#pragma unroll
    for (int mt = 0; mt < 4; ++mt) {
        rowA[mt] = wm * 64 + mt * 16 + (lane & 15);
        rmA[mt]  = rowA[mt] & 7;
    }
    int rowB[2], rmB[2];
#pragma unroll
    for (int p = 0; p < 2; ++p) {
        rowB[p] = wn * 32 + p * 16 + (lane & 15);
        rmB[p]  = rowB[p] & 7;
    }
    const int ua = lane >> 4;           // 16B-unit selector within k16

    float acc[4][4][4];
#pragma unroll
    for (int i = 0; i < 4; ++i)
#pragma unroll
        for (int j = 0; j < 4; ++j)
#pragma unroll
            for (int k = 0; k < 4; ++k) acc[i][j][k] = 0.f;

    issue(sb, 0);
    asm volatile("cp.async.commit_group;" ::: "memory");
    issue(sb + STAGE, 64);
    asm volatile("cp.async.commit_group;" ::: "memory");

    int cs = 0, ws = 2;
    for (int t = 0; t < KTH; ++t) {
        asm volatile("cp.async.wait_group 1;" ::: "memory");
        __syncthreads();                    // stage t visible; slot ws free

        if (t + 2 < KTH)
            issue(sb + ws * STAGE, (t + 2) * 64);
        asm volatile("cp.async.commit_group;" ::: "memory");
        ws = (ws == 2) ? 0 : ws + 1;

        const uint32_t st = sb + cs * STAGE;
        cs = (cs == 2) ? 0 : cs + 1;
#pragma unroll
        for (int ks = 0; ks < 4; ++ks) {    // 4 x k16 per 64-K tile
            uint32_t af[4][4], bf[2][4];
#pragma unroll
            for (int mt = 0; mt < 4; ++mt) {
                const uint32_t ad = st + rowA[mt] * 128 +
                                    (((ks * 2 + ua) ^ rmA[mt]) << 4);
                LDSM4(af[mt], ad);
            }
#pragma unroll
            for (int p = 0; p < 2; ++p) {
                const uint32_t bd = st + OFF_B + rowB[p] * 128 +
                                    (((ks * 2 + ua) ^ rmB[p]) << 4);
                LDSM4(bf[p], bd);
            }
#pragma unroll
            for (int mt = 0; mt < 4; ++mt) {
#pragma unroll
                for (int nt = 0; nt < 4; ++nt) {
                    const int p = nt >> 1, s = nt & 1;
                    MMAH(acc[mt][nt], af[mt], bf[p][s], bf[p][s + 2]);
                }
            }
        }
    }

    // --- epilogue: register frags -> GMEM with bias ---
#pragma unroll
    for (int mt = 0; mt < 4; ++mt) {
#pragma unroll
        for (int nt = 0; nt < 4; ++nt) {
            const float* c = acc[mt][nt];
            const int row = bm * 128 + wm * 64 + mt * 16 + (lane >> 2);
            const int col = bn * 128 + wn * 32 + nt * 8 + (lane & 3) * 2;
            const float b0 = __ldg(bias + col);
            const float b1 = __ldg(bias + col + 1);
            *(float2*)(C + (size_t)row * N + col) =
                make_float2(c[0] + b0, c[1] + b1);
            *(float2*)(C + (size_t)(row + 8) * N + col) =
                make_float2(c[2] + b0, c[3] + b1);
        }
    }
}

// ---------------------------------------------------------------------------
// MMA attention (tf32 internals, unchanged from R15): one CTA per
// (window, head), 128 threads (4 warps), warp = 32 query rows.
// Output now written as fp16 (feeds fp16 GEMM3).
// ---------------------------------------------------------------------------
#define ATTN_SMEM 103424

__global__ __launch_bounds__(128)
void attn_kernel(const float* __restrict__ qkv, __half* __restrict__ att)
{
    extern __shared__ float sm[];
    float* Qs = sm;             // 128 x 68
    float* Ks = sm + 8704;      // 128 x 68
    float* Vt = sm + 17408;     // 64 x 132  (Vt[d][key])

    const int w    = blockIdx.x;
    const int h    = blockIdx.y;
    const int tid  = threadIdx.x;
    const int lane = tid & 31;
    const int wi   = tid >> 5;

    const size_t base = (size_t)w * WIN * QKVDIM + h * HD;

    {
        const float4* Qg = (const float4*)(qkv + base + (size_t)tid * QKVDIM);
        const float4* Kg = (const float4*)(qkv + base + (size_t)tid * QKVDIM + HDIM);
        const float4* Vg = (const float4*)(qkv + base + (size_t)tid * QKVDIM + 2 * HDIM);
        float* qr = Qs + tid * 68;
        float* kr = Ks + tid * 68;
#pragma unroll
        for (int i = 0; i < 16; ++i) {
            float4 q = Qg[i], k = Kg[i], v = Vg[i];
            qr[4*i+0] = rna_tf32(q.x * 0.125f);
            qr[4*i+1] = rna_tf32(q.y * 0.125f);
            qr[4*i+2] = rna_tf32(q.z * 0.125f);
            qr[4*i+3] = rna_tf32(q.w * 0.125f);
            kr[4*i+0] = rna_tf32(k.x);
            kr[4*i+1] = rna_tf32(k.y);
            kr[4*i+2] = rna_tf32(k.z);
            kr[4*i+3] = rna_tf32(k.w);
            Vt[(4*i+0) * 132 + tid] = rna_tf32(v.x);
            Vt[(4*i+1) * 132 + tid] = rna_tf32(v.y);
            Vt[(4*i+2) * 132 + tid] = rna_tf32(v.z);
            Vt[(4*i+3) * 132 + tid] = rna_tf32(v.w);
        }
    }
    __syncthreads();

    const uint32_t qb = smem_u32(Qs);
    const uint32_t kbs = smem_u32(Ks);
    const uint32_t vb = smem_u32(Vt);

    int rowA[2];
    rowA[0] = wi * 32 + ((lane >> 3) & 1) * 8 + (lane & 7);
    rowA[1] = rowA[0] + 16;
    const int uaA = lane >> 4;
    int rowK[2];
    rowK[0] = (lane >> 4) * 8 + (lane & 7);
    rowK[1] = rowK[0] + 16;
    const int uaB = (lane >> 3) & 1;
    int rowV[4];
#pragma unroll
    for (int p = 0; p < 4; ++p)
        rowV[p] = p * 16 + (lane >> 4) * 8 + (lane & 7);

    float o[2][8][4];
#pragma unroll
    for (int mt = 0; mt < 2; ++mt)
#pragma unroll
        for (int nt = 0; nt < 8; ++nt)
#pragma unroll
            for (int k = 0; k < 4; ++k) o[mt][nt][k] = 0.f;
    float mrow[2][2] = {{-1e30f, -1e30f}, {-1e30f, -1e30f}};
    float lrow[2][2] = {{0.f, 0.f}, {0.f, 0.f}};

    const int  srcl = (lane & 28) | ((lane >> 1) & 1);
    const int  srch = srcl + 2;
    const bool oddl = (lane & 1) != 0;

    for (int kb = 0; kb < 4; ++kb) {
        float sacc[2][4][4];
#pragma unroll
        for (int mt = 0; mt < 2; ++mt)
#pragma unroll
            for (int nt = 0; nt < 4; ++nt)
#pragma unroll
                for (int k = 0; k < 4; ++k) sacc[mt][nt][k] = 0.f;
#pragma unroll
        for (int ks = 0; ks < 8; ++ks) {
            uint32_t af[2][4], bf[2][4];
#pragma unroll
            for (int mt = 0; mt < 2; ++mt)
                LDSM4(af[mt], qb + rowA[mt] * 272 + (ks * 2 + uaA) * 16);
#pragma unroll
            for (int p = 0; p < 2; ++p)
                LDSM4(bf[p], kbs + (kb * 32 + rowK[p]) * 272 + (ks * 2 + uaB) * 16);
#pragma unroll
            for (int mt = 0; mt < 2; ++mt)
#pragma unroll
                for (int nt = 0; nt < 4; ++nt) {
                    const int p = nt >> 1, s = (nt & 1) * 2;
                    MMAT(sacc[mt][nt], af[mt], bf[p][s], bf[p][s + 1]);
                }
        }

        float sc[2][2];
#pragma unroll
        for (int mt = 0; mt < 2; ++mt)
#pragma unroll
            for (int rh = 0; rh < 2; ++rh) {
                float bm = sacc[mt][0][rh * 2];
#pragma unroll
                for (int nt = 0; nt < 4; ++nt) {
                    bm = fmaxf(bm, sacc[mt][nt][rh * 2]);
                    bm = fmaxf(bm, sacc[mt][nt][rh * 2 + 1]);
                }
                bm = fmaxf(bm, __shfl_xor_sync(0xFFFFFFFFu, bm, 1));
                bm = fmaxf(bm, __shfl_xor_sync(0xFFFFFFFFu, bm, 2));
                const float mn = fmaxf(mrow[mt][rh], bm);
                sc[mt][rh] = __expf(mrow[mt][rh] - mn);
                mrow[mt][rh] = mn;
            }
#pragma unroll
        for (int mt = 0; mt < 2; ++mt)
#pragma unroll
            for (int rh = 0; rh < 2; ++rh) {
                float ps = 0.f;
#pragma unroll
                for (int nt = 0; nt < 4; ++nt) {
                    float p0 = rna_tf32(__expf(sacc[mt][nt][rh * 2]     - mrow[mt][rh]));
                    float p1 = rna_tf32(__expf(sacc[mt][nt][rh * 2 + 1] - mrow[mt][rh]));
                    sacc[mt][nt][rh * 2]     = p0;
                    sacc[mt][nt][rh * 2 + 1] = p1;
                    ps += p0 + p1;
                }
                ps += __shfl_xor_sync(0xFFFFFFFFu, ps, 1);
                ps += __shfl_xor_sync(0xFFFFFFFFu, ps, 2);
                lrow[mt][rh] = lrow[mt][rh] * sc[mt][rh] + ps;
            }
#pragma unroll
        for (int mt = 0; mt < 2; ++mt)
#pragma unroll
            for (int nt = 0; nt < 8; ++nt) {
                o[mt][nt][0] *= sc[mt][0];
                o[mt][nt][1] *= sc[mt][0];
                o[mt][nt][2] *= sc[mt][1];
                o[mt][nt][3] *= sc[mt][1];
            }

        uint32_t pa[2][4][4];
#pragma unroll
        for (int mt = 0; mt < 2; ++mt)
#pragma unroll
            for (int kt = 0; kt < 4; ++kt) {
                float t0, t1;
                t0 = __shfl_sync(0xFFFFFFFFu, sacc[mt][kt][0], srcl);
                t1 = __shfl_sync(0xFFFFFFFFu, sacc[mt][kt][1], srcl);
                pa[mt][kt][0] = __float_as_uint(oddl ? t1 : t0);
                t0 = __shfl_sync(0xFFFFFFFFu, sacc[mt][kt][2], srcl);
                t1 = __shfl_sync(0xFFFFFFFFu, sacc[mt][kt][3], srcl);
                pa[mt][kt][1] = __float_as_uint(oddl ? t1 : t0);
                t0 = __shfl_sync(0xFFFFFFFFu, sacc[mt][kt][0], srch);
                t1 = __shfl_sync(0xFFFFFFFFu, sacc[mt][kt][1], srch);
                pa[mt][kt][2] = __float_as_uint(oddl ? t1 : t0);
                t0 = __shfl_sync(0xFFFFFFFFu, sacc[mt][kt][2], srch);
                t1 = __shfl_sync(0xFFFFFFFFu, sacc[mt][kt][3], srch);
                pa[mt][kt][3] = __float_as_uint(oddl ? t1 : t0);
            }

#pragma unroll
        for (int kpv = 0; kpv < 4; ++kpv) {
            uint32_t bv[4][4];
#pragma unroll
            for (int p = 0; p < 4; ++p)
                LDSM4(bv[p], vb + rowV[p] * 528 + (kb * 8 + kpv * 2 + uaB) * 16);
#pragma unroll
            for (int mt = 0; mt < 2; ++mt)
#pragma unroll
                for (int nt = 0; nt < 8; ++nt) {
                    const int p = nt >> 1, s = (nt & 1) * 2;
                    MMAT(o[mt][nt], pa[mt][kpv], bv[p][s], bv[p][s + 1]);
                }
        }
    }

    float inv[2][2];
#pragma unroll
    for (int mt = 0; mt < 2; ++mt) {
        inv[mt][0] = 1.0f / lrow[mt][0];
        inv[mt][1] = 1.0f / lrow[mt][1];
    }
#pragma unroll
    for (int mt = 0; mt < 2; ++mt) {
        const int r0 = w * 128 + wi * 32 + mt * 16 + (lane >> 2);
#pragma unroll
        for (int nt = 0; nt < 8; ++nt) {
            const int col = h * 64 + nt * 8 + (lane & 3) * 2;
            *(__half2*)(att + (size_t)r0 * HDIM + col) =
                __floats2half2_rn(o[mt][nt][0] * inv[mt][0],
                                  o[mt][nt][1] * inv[mt][0]);
            *(__half2*)(att + (size_t)(r0 + 8) * HDIM + col) =
                __floats2half2_rn(o[mt][nt][2] * inv[mt][1],
                                  o[mt][nt][3] * inv[mt][1]);
        }
    }
}

// ---------------------------------------------------------------------------
extern "C" void kernel_launch(void* const* d_in, const int* in_sizes, int n_in,
                              void* d_out, int out_size)
{
    (void)in_sizes; (void)n_in; (void)out_size;
    const float* x     = (const float*)d_in[0];
    const float* w_in  = (const float*)d_in[1];
    const float* b_in  = (const float*)d_in[2];
    const float* w_out = (const float*)d_in[3];
    const float* b_out = (const float*)d_in[4];
    float* out = (float*)d_out;

    float* qkv;
    __half *xh, *wih, *woh, *att;
    cudaGetSymbolAddress((void**)&qkv, g_qkv);
    cudaGetSymbolAddress((void**)&xh,  g_xh);
    cudaGetSymbolAddress((void**)&wih, g_wih);
    cudaGetSymbolAddress((void**)&woh, g_woh);
    cudaGetSymbolAddress((void**)&att, g_att);

    cudaFuncSetAttribute(gemm_f16,
                         cudaFuncAttributeMaxDynamicSharedMemorySize, GEMM_SMEM);
    cudaFuncSetAttribute(attn_kernel,
                         cudaFuncAttributeMaxDynamicSharedMemorySize, ATTN_SMEM);

    // convert fp32 inputs to fp16 (rn)
    to_half<<<(M_TOK  * HDIM) / 2048, 256>>>((const float4*)x,     (uint4*)xh);
    to_half<<<(QKVDIM * HDIM) / 2048, 256>>>((const float4*)w_in,  (uint4*)wih);
    to_half<<<(HDIM   * HDIM) / 2048, 256>>>((const float4*)w_out, (uint4*)woh);

    // Stage 1: QKV projection (fp16 HMMA)
    gemm_f16<<<dim3(M_TOK / 128, QKVDIM / 128), 256, GEMM_SMEM>>>(
        xh, wih, b_in, qkv, QKVDIM);

    // Stage 2: windowed attention (tf32 MMA, flash softmax, emits fp16)
    attn_kernel<<<dim3(NWIN, NHEAD), 128, ATTN_SMEM>>>(qkv, att);

    // Stage 3: output projection (fp16 HMMA)
    gemm_f16<<<dim3(M_TOK / 128, HDIM / 128), 256, GEMM_SMEM>>>(
        att, woh, b_out, out, HDIM);
}

// round 17
// speedup vs baseline: 2.7495x; 1.2171x over previous
#include <cuda_runtime.h>
#include <cuda_fp16.h>
#include <cstdint>

// ---------------------------------------------------------------------------
// LocalWindowTransformer on sm_103 — fp16 HMMA end-to-end interior.
//   GEMM1: qkv(fp16) = x @ Win^T + b_in   [16384 x 3072], K=1024  (fp16 MMA)
//   attn : per (window, head) flash softmax(qk^T/8)v               (fp16 MMA)
//   GEMM3: out(fp32) = att @ Wout^T + b_out [16384 x 1024]         (fp16 MMA)
// R17: attention moved to fp16 m16n8k16 (half the MMAs/bytes of tf32); the
//      S-accumulator layout == P A-fragment layout after half2 packing, so
//      the P conversion needs NO shuffles. GEMM1 writes fp16 qkv directly.
// ---------------------------------------------------------------------------

#define M_TOK   16384
#define HDIM    1024
#define QKVDIM  3072
#define NHEAD   16
#define HD      64
#define WIN     128
#define NWIN    128

// ---- device scratch (no cudaMalloc allowed) --------------------------------
__device__ __half g_qkv [(size_t)M_TOK * QKVDIM];    // 96 MiB fp16
__device__ __half g_xh  [(size_t)M_TOK * HDIM];
__device__ __half g_wih [(size_t)QKVDIM * HDIM];
__device__ __half g_woh [(size_t)HDIM * HDIM];
__device__ __half g_att [(size_t)M_TOK * HDIM];

// ---- helpers ---------------------------------------------------------------
__device__ __forceinline__ uint32_t smem_u32(const void* p) {
    uint32_t a;
    asm("{ .reg .u64 t; cvta.to.shared.u64 t, %1; cvt.u32.u64 %0, t; }"
        : "=r"(a) : "l"(p));
    return a;
}
__device__ __forceinline__ void cp16(uint32_t dst, const void* src) {
    asm volatile("cp.async.cg.shared.global [%0], [%1], 16;"
                 :: "r"(dst), "l"(src));
}

#define LDSM4(r, a) \
    asm volatile("ldmatrix.sync.aligned.m8n8.x4.shared.b16 {%0,%1,%2,%3}, [%4];" \
                 : "=r"((r)[0]), "=r"((r)[1]), "=r"((r)[2]), "=r"((r)[3]) \
                 : "r"(a))

#define MMAH(c, a, b0, b1) \
    asm volatile("mma.sync.aligned.m16n8k16.row.col.f32.f16.f16.f32 " \
                 "{%0,%1,%2,%3}, {%4,%5,%6,%7}, {%8,%9}, {%0,%1,%2,%3};" \
                 : "+f"((c)[0]), "+f"((c)[1]), "+f"((c)[2]), "+f"((c)[3]) \
                 : "r"((a)[0]), "r"((a)[1]), "r"((a)[2]), "r"((a)[3]), \
                   "r"(b0), "r"(b1))

__device__ __forceinline__ uint32_t h2pack(float a, float b) {
    __half2 h = __floats2half2_rn(a, b);
    return *(uint32_t*)&h;
}

// ---------------------------------------------------------------------------
// convert fp32 -> fp16 (rn). 1 thread = 8 values (one uint4 out).
// ---------------------------------------------------------------------------
__global__ __launch_bounds__(256)
void to_half(const float4* __restrict__ src, uint4* __restrict__ dst)
{
    int u = blockIdx.x * 256 + threadIdx.x;
    float4 a = src[2 * u], b = src[2 * u + 1];
    __half2 h0 = __floats2half2_rn(a.x, a.y);
    __half2 h1 = __floats2half2_rn(a.z, a.w);
    __half2 h2 = __floats2half2_rn(b.x, b.y);
    __half2 h3 = __floats2half2_rn(b.z, b.w);
    uint4 o;
    o.x = *(uint32_t*)&h0; o.y = *(uint32_t*)&h1;
    o.z = *(uint32_t*)&h2; o.w = *(uint32_t*)&h3;
    dst[u] = o;
}

// ---------------------------------------------------------------------------
// fp16 NT GEMM: C[M,N] = A[M,1024] * B[N,1024]^T + bias (fp32 accum)
// BM=BN=128, BK=64 (128B rows), 256 threads (8 warps 2x4), warp tile 64x32,
// XOR-swizzled smem, 3-stage cp.async, 2 CTAs/SM.
// HALF_OUT selects fp16 vs fp32 C.
// ---------------------------------------------------------------------------
#define OFF_B  16384
#define STAGE  32768
#define KTH    16               /* 1024 / 64 */
#define GEMM_SMEM (3 * STAGE)   /* 98304 B */

template <int HALF_OUT>
__global__ __launch_bounds__(256, 2)
void gemm_f16(const __half* __restrict__ A, const __half* __restrict__ B,
              const float* __restrict__ bias, void* __restrict__ Cv, int N)
{
    extern __shared__ char smem_raw[];
    const uint32_t sb = smem_u32(smem_raw);

    const int tid  = threadIdx.x;
    const int lane = tid & 31;
    const int wid  = tid >> 5;
    const int wm   = wid & 1;
    const int wn   = wid >> 1;
    const int bm   = blockIdx.x;
    const int bn   = blockIdx.y;

    const int lrow = tid >> 1;
    const int lhu  = (tid & 1) * 4;
    const int lrm  = lrow & 7;
    uint32_t dstu[4];
#pragma unroll
    for (int i = 0; i < 4; ++i)
        dstu[i] = lrow * 128 + (((lhu + i) ^ lrm) << 4);

    const __half* pA = A + (size_t)(bm * 128 + lrow) * 1024 + lhu * 8;
    const __half* pB = B + (size_t)(bn * 128 + lrow) * 1024 + lhu * 8;

    auto issue = [&](uint32_t st, int ko) {
#pragma unroll
        for (int i = 0; i < 4; ++i) {
            cp16(st + dstu[i],         pA + ko + i * 8);
            cp16(st + OFF_B + dstu[i], pB + ko + i * 8);
        }
    };

    int rowA[4], rmA[4];
#pragma unroll
    for (int mt = 0; mt < 4; ++mt) {
        rowA[mt] = wm * 64 + mt * 16 + (lane & 15);
        rmA[mt]  = rowA[mt] & 7;
    }
    int rowB[2], rmB[2];
#pragma unroll
    for (int p = 0; p < 2; ++p) {
        rowB[p] = wn * 32 + p * 16 + (lane & 15);
        rmB[p]  = rowB[p] & 7;
    }
    const int ua = lane >> 4;

    float acc[4][4][4];
#pragma unroll
    for (int i = 0; i < 4; ++i)
#pragma unroll
        for (int j = 0; j < 4; ++j)
#pragma unroll
            for (int k = 0; k < 4; ++k) acc[i][j][k] = 0.f;

    issue(sb, 0);
    asm volatile("cp.async.commit_group;" ::: "memory");
    issue(sb + STAGE, 64);
    asm volatile("cp.async.commit_group;" ::: "memory");

    int cs = 0, ws = 2;
    for (int t = 0; t < KTH; ++t) {
        asm volatile("cp.async.wait_group 1;" ::: "memory");
        __syncthreads();

        if (t + 2 < KTH)
            issue(sb + ws * STAGE, (t + 2) * 64);
        asm volatile("cp.async.commit_group;" ::: "memory");
        ws = (ws == 2) ? 0 : ws + 1;

        const uint32_t st = sb + cs * STAGE;
        cs = (cs == 2) ? 0 : cs + 1;
#pragma unroll
        for (int ks = 0; ks < 4; ++ks) {
            uint32_t af[4][4], bf[2][4];
#pragma unroll
            for (int mt = 0; mt < 4; ++mt) {
                const uint32_t ad = st + rowA[mt] * 128 +
                                    (((ks * 2 + ua) ^ rmA[mt]) << 4);
                LDSM4(af[mt], ad);
            }
#pragma unroll
            for (int p = 0; p < 2; ++p) {
                const uint32_t bd = st + OFF_B + rowB[p] * 128 +
                                    (((ks * 2 + ua) ^ rmB[p]) << 4);
                LDSM4(bf[p], bd);
            }
#pragma unroll
            for (int mt = 0; mt < 4; ++mt) {
#pragma unroll
                for (int nt = 0; nt < 4; ++nt) {
                    const int p = nt >> 1, s = nt & 1;
                    MMAH(acc[mt][nt], af[mt], bf[p][s], bf[p][s + 2]);
                }
            }
        }
    }

#pragma unroll
    for (int mt = 0; mt < 4; ++mt) {
#pragma unroll
        for (int nt = 0; nt < 4; ++nt) {
            const float* c = acc[mt][nt];
            const int row = bm * 128 + wm * 64 + mt * 16 + (lane >> 2);
            const int col = bn * 128 + wn * 32 + nt * 8 + (lane & 3) * 2;
            const float b0 = __ldg(bias + col);
            const float b1 = __ldg(bias + col + 1);
            if (HALF_OUT) {
                __half* C = (__half*)Cv;
                __half2 h0 = __floats2half2_rn(c[0] + b0, c[1] + b1);
                __half2 h1 = __floats2half2_rn(c[2] + b0, c[3] + b1);
                *(__half2*)(C + (size_t)row * N + col) = h0;
                *(__half2*)(C + (size_t)(row + 8) * N + col) = h1;
            } else {
                float* C = (float*)Cv;
                *(float2*)(C + (size_t)row * N + col) =
                    make_float2(c[0] + b0, c[1] + b1);
                *(float2*)(C + (size_t)(row + 8) * N + col) =
                    make_float2(c[2] + b0, c[3] + b1);
            }
        }
    }
}

// ---------------------------------------------------------------------------
// fp16 MMA attention: one CTA per (window, head), 128 threads (4 warps),
// warp = 32 query rows, flash softmax over 4 key-blocks of 32.
// smem: Q[128 x 72h] / K[128 x 72h] (144B rows, conflict-free ldmatrix),
//       Vt[64 x 136h] (V transposed, 272B rows).
// P conversion: S-acc (m16n8k16 f32) half2-packs DIRECTLY into the A-frag
// layout of the PV MMA — no shuffles.
// ---------------------------------------------------------------------------
#define ATTN_SMEM 54272

__global__ __launch_bounds__(128)
void attn_kernel(const __half* __restrict__ qkv, __half* __restrict__ att)
{
    extern __shared__ __half smh[];
    __half* Qs = smh;               // 128 x 72
    __half* Ks = smh + 9216;        // 128 x 72
    __half* Vt = smh + 18432;       // 64 x 136  (Vt[d][key])

    const int w    = blockIdx.x;
    const int h    = blockIdx.y;
    const int tid  = threadIdx.x;
    const int lane = tid & 31;
    const int wi   = tid >> 5;

    const size_t base = (size_t)w * WIN * QKVDIM + h * HD;

    // ---- fill smem (Q pre-scaled by 1/8; exact in fp16) ----
    {
        const uint4* Qg = (const uint4*)(qkv + base + (size_t)tid * QKVDIM);
        const uint4* Kg = (const uint4*)(qkv + base + (size_t)tid * QKVDIM + HDIM);
        const uint4* Vg = (const uint4*)(qkv + base + (size_t)tid * QKVDIM + 2 * HDIM);
        const __half2 s8 = __floats2half2_rn(0.125f, 0.125f);
        uint4* qr = (uint4*)(Qs + tid * 72);
        uint4* kr = (uint4*)(Ks + tid * 72);
#pragma unroll
        for (int i = 0; i < 8; ++i) {
            uint4 q = Qg[i];
            __half2* qh = (__half2*)&q;
            qh[0] = __hmul2(qh[0], s8); qh[1] = __hmul2(qh[1], s8);
            qh[2] = __hmul2(qh[2], s8); qh[3] = __hmul2(qh[3], s8);
            qr[i] = q;
            kr[i] = Kg[i];
            uint4 v = Vg[i];
            const __half* vh = (const __half*)&v;
#pragma unroll
            for (int j = 0; j < 8; ++j)
                Vt[(i * 8 + j) * 136 + tid] = vh[j];
        }
    }
    __syncthreads();

    const uint32_t qb = smem_u32(Qs);
    const uint32_t kb_ = smem_u32(Ks);
    const uint32_t vb = smem_u32(Vt);

    // fragment rows (R3-verified fp16 b16 pattern, padded rows, no swizzle)
    int rowA[2];
    rowA[0] = wi * 32 + (lane & 15);
    rowA[1] = rowA[0] + 16;
    int rowV[4];
#pragma unroll
    for (int p = 0; p < 4; ++p)
        rowV[p] = p * 16 + (lane & 15);
    const int ua = lane >> 4;

    float o[2][8][4];
#pragma unroll
    for (int mt = 0; mt < 2; ++mt)
#pragma unroll
        for (int nt = 0; nt < 8; ++nt)
#pragma unroll
            for (int k = 0; k < 4; ++k) o[mt][nt][k] = 0.f;
    float mrow[2][2] = {{-1e30f, -1e30f}, {-1e30f, -1e30f}};
    float lrow[2][2] = {{0.f, 0.f}, {0.f, 0.f}};

    for (int kb = 0; kb < 4; ++kb) {
        // ---- S = Q K^T (32-key block): 4 k16 steps ----
        float sacc[2][4][4];
#pragma unroll
        for (int mt = 0; mt < 2; ++mt)
#pragma unroll
            for (int nt = 0; nt < 4; ++nt)
#pragma unroll
                for (int k = 0; k < 4; ++k) sacc[mt][nt][k] = 0.f;
#pragma unroll
        for (int ks = 0; ks < 4; ++ks) {
            uint32_t af[2][4], bf[2][4];
#pragma unroll
            for (int mt = 0; mt < 2; ++mt)
                LDSM4(af[mt], qb + (rowA[mt] * 72 + (ks * 2 + ua) * 8) * 2);
#pragma unroll
            for (int p = 0; p < 2; ++p)
                LDSM4(bf[p], kb_ + ((kb * 32 + p * 16 + (lane & 15)) * 72 +
                                    (ks * 2 + ua) * 8) * 2);
#pragma unroll
            for (int mt = 0; mt < 2; ++mt)
#pragma unroll
                for (int nt = 0; nt < 4; ++nt) {
                    const int p = nt >> 1, s = nt & 1;
                    MMAH(sacc[mt][nt], af[mt], bf[p][s], bf[p][s + 2]);
                }
        }

        // ---- online softmax update ----
        float sc[2][2];
#pragma unroll
        for (int mt = 0; mt < 2; ++mt)
#pragma unroll
            for (int rh = 0; rh < 2; ++rh) {
                float bm = sacc[mt][0][rh * 2];
#pragma unroll
                for (int nt = 0; nt < 4; ++nt) {
                    bm = fmaxf(bm, sacc[mt][nt][rh * 2]);
                    bm = fmaxf(bm, sacc[mt][nt][rh * 2 + 1]);
                }
                bm = fmaxf(bm, __shfl_xor_sync(0xFFFFFFFFu, bm, 1));
                bm = fmaxf(bm, __shfl_xor_sync(0xFFFFFFFFu, bm, 2));
                const float mn = fmaxf(mrow[mt][rh], bm);
                sc[mt][rh] = __expf(mrow[mt][rh] - mn);
                mrow[mt][rh] = mn;
            }
#pragma unroll
        for (int mt = 0; mt < 2; ++mt)
#pragma unroll
            for (int rh = 0; rh < 2; ++rh) {
                float ps = 0.f;
#pragma unroll
                for (int nt = 0; nt < 4; ++nt) {
                    float p0 = __expf(sacc[mt][nt][rh * 2]     - mrow[mt][rh]);
                    float p1 = __expf(sacc[mt][nt][rh * 2 + 1] - mrow[mt][rh]);
                    sacc[mt][nt][rh * 2]     = p0;
                    sacc[mt][nt][rh * 2 + 1] = p1;
                    ps += p0 + p1;
                }
                ps += __shfl_xor_sync(0xFFFFFFFFu, ps, 1);
                ps += __shfl_xor_sync(0xFFFFFFFFu, ps, 2);
                lrow[mt][rh] = lrow[mt][rh] * sc[mt][rh] + ps;
            }
#pragma unroll
        for (int mt = 0; mt < 2; ++mt)
#pragma unroll
            for (int nt = 0; nt < 8; ++nt) {
                o[mt][nt][0] *= sc[mt][0];
                o[mt][nt][1] *= sc[mt][0];
                o[mt][nt][2] *= sc[mt][1];
                o[mt][nt][3] *= sc[mt][1];
            }

        // ---- P: acc -> fp16 A-fragments (layout identity, no shuffles) ----
        uint32_t pa[2][2][4];
#pragma unroll
        for (int mt = 0; mt < 2; ++mt)
#pragma unroll
            for (int kt = 0; kt < 2; ++kt) {
                pa[mt][kt][0] = h2pack(sacc[mt][2*kt][0],     sacc[mt][2*kt][1]);
                pa[mt][kt][1] = h2pack(sacc[mt][2*kt][2],     sacc[mt][2*kt][3]);
                pa[mt][kt][2] = h2pack(sacc[mt][2*kt+1][0],   sacc[mt][2*kt+1][1]);
                pa[mt][kt][3] = h2pack(sacc[mt][2*kt+1][2],   sacc[mt][2*kt+1][3]);
            }

        // ---- O += P V  (B from transposed V; 2 k16 steps) ----
#pragma unroll
        for (int kt = 0; kt < 2; ++kt) {
            uint32_t bv[4][4];
#pragma unroll
            for (int p = 0; p < 4; ++p)
                LDSM4(bv[p], vb + (rowV[p] * 136 + (kb * 4 + kt * 2 + ua) * 8) * 2);
#pragma unroll
            for (int mt = 0; mt < 2; ++mt)
#pragma unroll
                for (int nt = 0; nt < 8; ++nt) {
                    const int p = nt >> 1, s = nt & 1;
                    MMAH(o[mt][nt], pa[mt][kt], bv[p][s], bv[p][s + 2]);
                }
        }
    }

    // ---- normalize + store fp16 ----
    float inv[2][2];
#pragma unroll
    for (int mt = 0; mt < 2; ++mt) {
        inv[mt][0] = 1.0f / lrow[mt][0];
        inv[mt][1] = 1.0f / lrow[mt][1];
    }
#pragma unroll
    for (int mt = 0; mt < 2; ++mt) {
        const int r0 = w * 128 + wi * 32 + mt * 16 + (lane >> 2);
#pragma unroll
        for (int nt = 0; nt < 8; ++nt) {
            const int col = h * 64 + nt * 8 + (lane & 3) * 2;
            *(__half2*)(att + (size_t)r0 * HDIM + col) =
                __floats2half2_rn(o[mt][nt][0] * inv[mt][0],
                                  o[mt][nt][1] * inv[mt][0]);
            *(__half2*)(att + (size_t)(r0 + 8) * HDIM + col) =
                __floats2half2_rn(o[mt][nt][2] * inv[mt][1],
                                  o[mt][nt][3] * inv[mt][1]);
        }
    }
}

// ---------------------------------------------------------------------------
extern "C" void kernel_launch(void* const* d_in, const int* in_sizes, int n_in,
                              void* d_out, int out_size)
{
    (void)in_sizes; (void)n_in; (void)out_size;
    const float* x     = (const float*)d_in[0];
    const float* w_in  = (const float*)d_in[1];
    const float* b_in  = (const float*)d_in[2];
    const float* w_out = (const float*)d_in[3];
    const float* b_out = (const float*)d_in[4];
    float* out = (float*)d_out;

    __half *qkv, *xh, *wih, *woh, *att;
    cudaGetSymbolAddress((void**)&qkv, g_qkv);
    cudaGetSymbolAddress((void**)&xh,  g_xh);
    cudaGetSymbolAddress((void**)&wih, g_wih);
    cudaGetSymbolAddress((void**)&woh, g_woh);
    cudaGetSymbolAddress((void**)&att, g_att);

    cudaFuncSetAttribute(gemm_f16<1>,
                         cudaFuncAttributeMaxDynamicSharedMemorySize, GEMM_SMEM);
    cudaFuncSetAttribute(gemm_f16<0>,
                         cudaFuncAttributeMaxDynamicSharedMemorySize, GEMM_SMEM);
    cudaFuncSetAttribute(attn_kernel,
                         cudaFuncAttributeMaxDynamicSharedMemorySize, ATTN_SMEM);

    // convert fp32 inputs to fp16 (rn)
    to_half<<<(M_TOK  * HDIM) / 2048, 256>>>((const float4*)x,     (uint4*)xh);
    to_half<<<(QKVDIM * HDIM) / 2048, 256>>>((const float4*)w_in,  (uint4*)wih);
    to_half<<<(HDIM   * HDIM) / 2048, 256>>>((const float4*)w_out, (uint4*)woh);

    // Stage 1: QKV projection -> fp16 qkv
    gemm_f16<1><<<dim3(M_TOK / 128, QKVDIM / 128), 256, GEMM_SMEM>>>(
        xh, wih, b_in, qkv, QKVDIM);

    // Stage 2: windowed attention (fp16 MMA, flash softmax, fp16 out)
    attn_kernel<<<dim3(NWIN, NHEAD), 128, ATTN_SMEM>>>(qkv, att);

    // Stage 3: output projection -> fp32 out
    gemm_f16<0><<<dim3(M_TOK / 128, HDIM / 128), 256, GEMM_SMEM>>>(
        att, woh, b_out, out, HDIM);
}